// round 8
// baseline (speedup 1.0000x reference)
// Resubmission of round-7 kernel: previous bench failed with a harness-side
// "device busy or unavailable" before any kernel ran (transient infra).
#include <cuda_runtime.h>
#include <math.h>

#define DIMV 256
#define HEADSV 8
#define BSZ 8
#define NN 1024

typedef unsigned long long u64;

// ---- scratch (device globals: no allocations allowed) ----
__device__ float g_fp[BSZ * NN * DIMV * HEADSV];    // 64 MB  feat_proj [8192][2048]
__device__ float g_attn[BSZ * NN * DIMV * HEADSV];  // 64 MB  attn out  [8192][2048]
__device__ float g_qv[BSZ * HEADSV * NN];
__device__ float g_kv[BSZ * HEADSV * NN];
__device__ float g_Ae[BSZ * HEADSV * NN];
__device__ float g_Be[BSZ * HEADSV * NN];
__device__ float g_Ce[BSZ * HEADSV * NN];
__device__ float g_De[BSZ * HEADSV * NN];
// adjacency bitmasks: per (b*1024+i, jtile) one u64 of local-j bits (1 MB)
__device__ u64 g_mask[BSZ * NN * 16];

// ---- packed f32x2 helpers (sm_103a) ----
__device__ __forceinline__ u64 pack2(float x, float y) {
    u64 r; asm("mov.b64 %0, {%1, %2};" : "=l"(r) : "f"(x), "f"(y)); return r;
}
__device__ __forceinline__ void unpack2(u64 v, float &x, float &y) {
    asm("mov.b64 {%0, %1}, %2;" : "=f"(x), "=f"(y) : "l"(v));
}
__device__ __forceinline__ void fma2(u64 &d, u64 a, u64 b) {
    asm("fma.rn.f32x2 %0, %1, %2, %0;" : "+l"(d) : "l"(a), "l"(b));
}

// ============================================================================
// Adjacency -> bitmasks: warp per row, 16 j-tiles of 64 bits each.
// ============================================================================
__global__ void mask_kernel(const float* __restrict__ adj)
{
    int bi   = blockIdx.x * 8 + (threadIdx.x >> 5);   // 0..8191
    int lane = threadIdx.x & 31;
    const float* row = adj + (size_t)bi * 1024;
    #pragma unroll
    for (int jt = 0; jt < 16; jt++) {
        unsigned m1 = __ballot_sync(0xffffffffu, row[jt * 64 + lane] != 0.f);
        unsigned m2 = __ballot_sync(0xffffffffu, row[jt * 64 + 32 + lane] != 0.f);
        if (lane == 0) g_mask[bi * 16 + jt] = (u64)m1 | ((u64)m2 << 32);
    }
}

// ============================================================================
// f32x2 tiled GEMM: C[M][256-window] = A[M][K] @ B[K][ldn] (+bias, +epi)
// A panel kk-major so 2 rows' broadcast operands come from 1 LDS.128.
// EPI 0: +bias.  EPI 1: +bias +resid, sigmoid.  EPI 2: +bias, and fused q/k
// scalar projections (dot of each 256-wide head row with qw/kw via warp shfl).
// ============================================================================
template<int BM, int EPI>
__global__ __launch_bounds__(256, 2)
void gemm_kernel(const float* __restrict__ A, const float* __restrict__ B,
                 const float* __restrict__ bias, const float* __restrict__ resid,
                 float* __restrict__ C, int K, int ldn,
                 const float* __restrict__ qw, const float* __restrict__ qb,
                 const float* __restrict__ kw, const float* __restrict__ kb)
{
    constexpr int KT  = 64;
    constexpr int RPT = BM / 8;
    constexpr int LDA = BM + 2;
    extern __shared__ __align__(16) char sm_raw[];
    u64* B2 = (u64*)sm_raw;        // [KT][128]  packed (c, c+128)
    u64* A2 = B2 + KT * 128;       // [KT][LDA]  packed (a, a), kk-major

    const int t   = threadIdx.x;
    const int txd = t & 31;
    const int tyi = t >> 5;
    const int m0  = blockIdx.x * BM;
    const int n0  = blockIdx.y * 256;

    u64 acc[RPT][4];
    #pragma unroll
    for (int r = 0; r < RPT; r++)
        #pragma unroll
        for (int d = 0; d < 4; d++) acc[r][d] = 0ULL;

    for (int k0 = 0; k0 < K; k0 += KT) {
        __syncthreads();
        #pragma unroll
        for (int r = 0; r < (KT * 128) / 256; r++) {
            int idx = t + r * 256;
            int j = idx >> 7, c = idx & 127;
            const float* br = B + (size_t)(k0 + j) * ldn + n0;
            B2[j * 128 + c] = pack2(br[c], br[c + 128]);
        }
        #pragma unroll
        for (int r = 0; r < (BM * KT) / 256; r++) {
            int idx = t + r * 256;
            int kk = idx & 63, mi = idx >> 6;
            float a = A[(size_t)(m0 + mi) * K + k0 + kk];
            A2[kk * LDA + mi] = pack2(a, a);
        }
        __syncthreads();
        #pragma unroll 8
        for (int kk = 0; kk < KT; kk++) {
            ulonglong2 v01 = *(const ulonglong2*)(B2 + kk * 128 + 2 * txd);
            ulonglong2 v23 = *(const ulonglong2*)(B2 + kk * 128 + 64 + 2 * txd);
            #pragma unroll
            for (int rr = 0; rr < RPT / 2; rr++) {
                ulonglong2 aa = *(const ulonglong2*)(A2 + kk * LDA + tyi * RPT + 2 * rr);
                fma2(acc[2*rr][0], aa.x, v01.x);
                fma2(acc[2*rr][1], aa.x, v01.y);
                fma2(acc[2*rr][2], aa.x, v23.x);
                fma2(acc[2*rr][3], aa.x, v23.y);
                fma2(acc[2*rr+1][0], aa.y, v01.x);
                fma2(acc[2*rr+1][1], aa.y, v01.y);
                fma2(acc[2*rr+1][2], aa.y, v23.x);
                fma2(acc[2*rr+1][3], aa.y, v23.y);
            }
        }
    }

    const int cA = n0 + 2 * txd;         // acc[r][0].lo , acc[r][1].lo at cA,cA+1
    const int cB = cA + 128;             // acc[r][0].hi , acc[r][1].hi
    const int cC = n0 + 64 + 2 * txd;    // acc[r][2].lo , acc[r][3].lo
    const int cD = cC + 128;             // acc[r][2].hi , acc[r][3].hi
    float bA0 = bias[cA], bA1 = bias[cA + 1];
    float bB0 = bias[cB], bB1 = bias[cB + 1];
    float bC0 = bias[cC], bC1 = bias[cC + 1];
    float bD0 = bias[cD], bD1 = bias[cD + 1];

    // per-thread q/k weight slices (head-local columns) for EPI 2
    float2 qwA, qwB, qwC, qwD, kwA, kwB, kwC, kwD;
    float qbv = 0.f, kbv = 0.f;
    if (EPI == 2) {
        qwA = *(const float2*)(qw + 2 * txd);
        qwB = *(const float2*)(qw + 128 + 2 * txd);
        qwC = *(const float2*)(qw + 64 + 2 * txd);
        qwD = *(const float2*)(qw + 192 + 2 * txd);
        kwA = *(const float2*)(kw + 2 * txd);
        kwB = *(const float2*)(kw + 128 + 2 * txd);
        kwC = *(const float2*)(kw + 64 + 2 * txd);
        kwD = *(const float2*)(kw + 192 + 2 * txd);
        qbv = qb[0]; kbv = kb[0];
    }

    #pragma unroll
    for (int r = 0; r < RPT; r++) {
        int m = m0 + tyi * RPT + r;
        float a0, a1, b0, b1, c0, c1, d0, d1;
        unpack2(acc[r][0], a0, a1);
        unpack2(acc[r][1], b0, b1);
        unpack2(acc[r][2], c0, c1);
        unpack2(acc[r][3], d0, d1);
        float xA0 = a0 + bA0, xA1 = b0 + bA1;
        float xB0 = a1 + bB0, xB1 = b1 + bB1;
        float xC0 = c0 + bC0, xC1 = d0 + bC1;
        float xD0 = c1 + bD0, xD1 = d1 + bD1;
        float* crow = C + (size_t)m * ldn;
        if (EPI == 1) {
            const float* rrow = resid + (size_t)m * ldn;
            float2 rA = *(const float2*)(rrow + cA);
            float2 rB = *(const float2*)(rrow + cB);
            float2 rC = *(const float2*)(rrow + cC);
            float2 rD = *(const float2*)(rrow + cD);
            xA0 = 1.0f / (1.0f + expf(-(xA0 + rA.x)));
            xA1 = 1.0f / (1.0f + expf(-(xA1 + rA.y)));
            xB0 = 1.0f / (1.0f + expf(-(xB0 + rB.x)));
            xB1 = 1.0f / (1.0f + expf(-(xB1 + rB.y)));
            xC0 = 1.0f / (1.0f + expf(-(xC0 + rC.x)));
            xC1 = 1.0f / (1.0f + expf(-(xC1 + rC.y)));
            xD0 = 1.0f / (1.0f + expf(-(xD0 + rD.x)));
            xD1 = 1.0f / (1.0f + expf(-(xD1 + rD.y)));
        }
        *(float2*)(crow + cA) = make_float2(xA0, xA1);
        *(float2*)(crow + cB) = make_float2(xB0, xB1);
        *(float2*)(crow + cC) = make_float2(xC0, xC1);
        *(float2*)(crow + cD) = make_float2(xD0, xD1);

        if (EPI == 2) {
            float sq = xA0 * qwA.x + xA1 * qwA.y + xB0 * qwB.x + xB1 * qwB.y
                     + xC0 * qwC.x + xC1 * qwC.y + xD0 * qwD.x + xD1 * qwD.y;
            float sk = xA0 * kwA.x + xA1 * kwA.y + xB0 * kwB.x + xB1 * kwB.y
                     + xC0 * kwC.x + xC1 * kwC.y + xD0 * kwD.x + xD1 * kwD.y;
            #pragma unroll
            for (int o = 16; o > 0; o >>= 1) {
                sq += __shfl_down_sync(0xffffffffu, sq, o);
                sk += __shfl_down_sync(0xffffffffu, sk, o);
            }
            if (txd == 0) {
                int b = m >> 10, n = m & 1023;
                int bh = b * HEADSV + blockIdx.y;   // head = n-window index
                g_qv[bh * NN + n] = sq + qbv;
                g_kv[bh * NN + n] = sk + kbv;
            }
        }
    }
}

// ============================================================================
// Per-head factored-exp vectors (softmax shift-invariant; all products <= 1):
//   m_i = leaky(q_i + kmax); A=e^{q-m}, C=e^{.01q-m}, B=e^{k}, D=e^{.01k}
//   exp(leaky(q_i+k_j) - m_i) = (q_i+k_j>=0) ? A_i*B_j : C_i*D_j
// ============================================================================
__global__ void abcd_kernel()
{
    __shared__ float red[256];
    int bh = blockIdx.x, t = threadIdx.x;
    const float* kv = g_kv + bh * NN;
    float m = -1e30f;
    for (int n = t; n < NN; n += 256) m = fmaxf(m, kv[n]);
    red[t] = m; __syncthreads();
    for (int s = 128; s > 0; s >>= 1) {
        if (t < s) red[t] = fmaxf(red[t], red[t + s]);
        __syncthreads();
    }
    float kmax = red[0];
    const float* qv = g_qv + bh * NN;
    for (int n = t; n < NN; n += 256) {
        float q = qv[n], k = kv[n];
        float xm = q + kmax;
        float mi = (xm >= 0.f) ? xm : 0.01f * xm;
        g_Ae[bh * NN + n] = expf(q - mi);
        g_Ce[bh * NN + n] = expf(0.01f * q - mi);
        g_Be[bh * NN + n] = expf(k);
        g_De[bh * NN + n] = expf(0.01f * k);
    }
}

// ============================================================================
// Sparse attention: CTA = (bh, 64-row i-tile), warp owns 8 rows (full 256 d).
// Per 64-col j-tile: stage V tile (packed (d,d+128) u64), per-j (k,B,D), and
// the 64 row-masks for this tile; then iterate set bits per row:
//   p = (q_i+k_j>=0) ? A_i*B_j : C_i*D_j   (masked entries are exactly 0,
//   matching the fp32 reference where exp(~-1e7) underflows);
//   l_i += p;  O_i += p * V_j  (4x fma.f32x2 per edge). Normalize by 1/l.
// ============================================================================
__global__ __launch_bounds__(256, 2)
void attn_kernel()
{
    extern __shared__ __align__(16) char sm_raw[];
    u64* V2 = (u64*)sm_raw;                 // [64][128] packed (d, d+128)
    float4* kbd = (float4*)(V2 + 64 * 128); // [64] (kv, B, D, 0)
    u64* msk = (u64*)(kbd + 64);            // [64] row masks for current tile

    const int t   = threadIdx.x;
    const int txd = t & 31;
    const int tyi = t >> 5;
    const int bh  = blockIdx.x;
    const int b   = bh >> 3, h = bh & 7;
    const int i0  = blockIdx.y * 64;
    const int bi0 = b * NN + i0;

    float qv[8], Ae[8], Ce[8], lr[8];
    #pragma unroll
    for (int r = 0; r < 8; r++) {
        int gi = bh * NN + i0 + tyi * 8 + r;
        qv[r] = g_qv[gi]; Ae[r] = g_Ae[gi]; Ce[r] = g_Ce[gi]; lr[r] = 0.f;
    }

    u64 acc[8][4];
    #pragma unroll
    for (int r = 0; r < 8; r++)
        #pragma unroll
        for (int d = 0; d < 4; d++) acc[r][d] = 0ULL;

    for (int jt = 0; jt < 16; jt++) {
        int j0 = jt * 64;
        __syncthreads();   // previous-tile readers done
        if (t < 64) msk[t] = g_mask[(bi0 + t) * 16 + jt];
        #pragma unroll
        for (int rr = 0; rr < 32; rr++) {
            int idx = t + rr * 256;
            int j = idx >> 7, c = idx & 127;
            const float* vrow = g_fp + (size_t)(b * NN + j0 + j) * 2048 + h * 256;
            V2[j * 128 + c] = pack2(vrow[c], vrow[c + 128]);
        }
        if (t < 64) {
            int gj = bh * NN + j0 + t;
            kbd[t] = make_float4(g_kv[gj], g_Be[gj], g_De[gj], 0.f);
        }
        __syncthreads();

        #pragma unroll
        for (int r = 0; r < 8; r++) {
            u64 m = msk[tyi * 8 + r];
            float qvr = qv[r], Aer = Ae[r], Cer = Ce[r];
            while (m) {
                int jl = __ffsll((long long)m) - 1;
                m &= m - 1;
                float4 kb = kbd[jl];
                float x = qvr + kb.x;
                float p = (x >= 0.f) ? Aer * kb.y : Cer * kb.z;
                lr[r] += p;
                u64 pp = pack2(p, p);
                ulonglong2 v01 = *(const ulonglong2*)(V2 + jl * 128 + 2 * txd);
                ulonglong2 v23 = *(const ulonglong2*)(V2 + jl * 128 + 64 + 2 * txd);
                fma2(acc[r][0], pp, v01.x);
                fma2(acc[r][1], pp, v01.y);
                fma2(acc[r][2], pp, v23.x);
                fma2(acc[r][3], pp, v23.y);
            }
        }
    }

    #pragma unroll
    for (int r = 0; r < 8; r++) {
        float l = lr[r];
        float inv = (l > 0.f) ? 1.0f / l : 0.f;
        float* orow = g_attn + (size_t)(b * NN + i0 + tyi * 8 + r) * 2048 + h * 256;
        float a0, a1, b0, b1, c0, c1, d0, d1;
        unpack2(acc[r][0], a0, a1);   // cols (2txd,    2txd+128)
        unpack2(acc[r][1], b0, b1);   // cols (2txd+1,  2txd+129)
        unpack2(acc[r][2], c0, c1);   // cols (64+2txd, 192+2txd)
        unpack2(acc[r][3], d0, d1);   // cols (65+2txd, 193+2txd)
        *(float2*)(orow + 2 * txd)       = make_float2(a0 * inv, b0 * inv);
        *(float2*)(orow + 128 + 2 * txd) = make_float2(a1 * inv, b1 * inv);
        *(float2*)(orow + 64 + 2 * txd)  = make_float2(c0 * inv, d0 * inv);
        *(float2*)(orow + 192 + 2 * txd) = make_float2(c1 * inv, d1 * inv);
    }
}

// ============================================================================
extern "C" void kernel_launch(void* const* d_in, const int* in_sizes, int n_in,
                              void* d_out, int out_size)
{
    const float* feats = (const float*)d_in[0];
    const float* adj   = (const float*)d_in[1];
    const float* fc_w  = (const float*)d_in[2];
    const float* fc_b  = (const float*)d_in[3];
    const float* q_w   = (const float*)d_in[4];
    const float* q_b   = (const float*)d_in[5];
    const float* k_w   = (const float*)d_in[6];
    const float* k_b   = (const float*)d_in[7];
    const float* fp_w  = (const float*)d_in[8];
    const float* fp_b  = (const float*)d_in[9];
    float* out = (float*)d_out;

    const int smem_g1 = (64 * 128 + 64 * 66) * 8;         // 99328
    const int smem_g3 = (64 * 128 + 64 * 34) * 8;         // 82944
    const int smem_at = 64 * 128 * 8 + 64 * 16 + 64 * 8;  // 67072

    cudaFuncSetAttribute(gemm_kernel<64, 2>, cudaFuncAttributeMaxDynamicSharedMemorySize, smem_g1);
    cudaFuncSetAttribute(gemm_kernel<32, 1>, cudaFuncAttributeMaxDynamicSharedMemorySize, smem_g3);
    cudaFuncSetAttribute(attn_kernel,        cudaFuncAttributeMaxDynamicSharedMemorySize, smem_at);

    float* fp_buf = nullptr;
    float* at_buf = nullptr;
    cudaGetSymbolAddress((void**)&fp_buf, g_fp);
    cudaGetSymbolAddress((void**)&at_buf, g_attn);

    // 1) adjacency bitmasks (shared across heads)
    mask_kernel<<<1024, 256>>>(adj);

    // 2) feat_proj = feats @ fc_w + fc_b, with fused q/k scalar projections
    gemm_kernel<64, 2><<<dim3(8192 / 64, 2048 / 256), 256, smem_g1>>>(
        feats, fc_w, fc_b, nullptr, fp_buf, 256, 2048, q_w, q_b, k_w, k_b);

    // 3) per-head kmax + factored exp vectors
    abcd_kernel<<<64, 256>>>();

    // 4) sparse masked-softmax attention (bitmask gather over edges)
    attn_kernel<<<dim3(64, 16), 256, smem_at>>>();

    // 5) out = sigmoid(attn_out @ fp_w + fp_b + feats)
    gemm_kernel<32, 1><<<dim3(8192 / 32, 1), 256, smem_g3>>>(
        at_buf, fp_w, fp_b, feats, out, 2048, 256,
        nullptr, nullptr, nullptr, nullptr);
}

// round 9
// speedup vs baseline: 1.3137x; 1.3137x over previous
#include <cuda_runtime.h>
#include <math.h>

#define DIMV 256
#define HEADSV 8
#define BSZ 8
#define NN 1024

typedef unsigned long long u64;

// ---- scratch (device globals: no allocations allowed) ----
__device__ float g_fp[BSZ * NN * DIMV * HEADSV];    // 64 MB  feat_proj [8192][2048]
__device__ float g_attn[BSZ * NN * DIMV * HEADSV];  // 64 MB  attn out  [8192][2048]
__device__ float g_qv[BSZ * HEADSV * NN];
__device__ float g_kv[BSZ * HEADSV * NN];
__device__ float4 g_kbd[BSZ * HEADSV * NN];         // (k, B=e^k, D=e^{.01k}, 0)
__device__ float4 g_qac[BSZ * HEADSV * NN];         // (q, A=e^{q-m}, C=e^{.01q-m}, 0)
// adjacency bitmasks, transposed: g_m32[jt*8192 + (b*1024+i)] = 32 j-bits (1 MB)
__device__ unsigned g_m32[32 * BSZ * NN];

// ---- packed f32x2 helpers (sm_103a) ----
__device__ __forceinline__ u64 pack2(float x, float y) {
    u64 r; asm("mov.b64 %0, {%1, %2};" : "=l"(r) : "f"(x), "f"(y)); return r;
}
__device__ __forceinline__ void unpack2(u64 v, float &x, float &y) {
    asm("mov.b64 {%0, %1}, %2;" : "=f"(x), "=f"(y) : "l"(v));
}
__device__ __forceinline__ void fma2(u64 &d, u64 a, u64 b) {
    asm("fma.rn.f32x2 %0, %1, %2, %0;" : "+l"(d) : "l"(a), "l"(b));
}
// ---- cp.async helpers ----
__device__ __forceinline__ void cpasync16(unsigned s, const void* g) {
    asm volatile("cp.async.ca.shared.global [%0], [%1], 16;" :: "r"(s), "l"(g));
}
#define CP_COMMIT() asm volatile("cp.async.commit_group;" ::: "memory")
#define CP_WAIT1()  asm volatile("cp.async.wait_group 1;" ::: "memory")
#define CP_WAIT0()  asm volatile("cp.async.wait_group 0;" ::: "memory")

__device__ __forceinline__ unsigned smem_u32(const void* p) {
    unsigned a;
    asm("{ .reg .u64 t; cvta.to.shared.u64 t, %1; cvt.u32.u64 %0, t; }"
        : "=r"(a) : "l"(p));
    return a;
}

// ============================================================================
// Adjacency -> transposed 32-bit masks: warp per row, 32 j-tiles of 32 bits.
// ============================================================================
__global__ void mask_kernel(const float* __restrict__ adj)
{
    int bi   = blockIdx.x * 8 + (threadIdx.x >> 5);   // 0..8191
    int lane = threadIdx.x & 31;
    const float* row = adj + (size_t)bi * 1024;
    #pragma unroll
    for (int jt = 0; jt < 32; jt++) {
        unsigned mm = __ballot_sync(0xffffffffu, row[jt * 32 + lane] != 0.f);
        if (lane == 0) g_m32[jt * 8192 + bi] = mm;
    }
}

// ============================================================================
// f32x2 tiled GEMM: C[M][256-window] = A[M][K] @ B[K][ldn] (+bias, +epi)
// A panel kk-major so 2 rows' broadcast operands come from 1 LDS.128.
// EPI 0: +bias.  EPI 1: +bias +resid, sigmoid.  EPI 2: +bias, and fused q/k
// scalar projections (dot of each 256-wide head row with qw/kw via warp shfl).
// ============================================================================
template<int BM, int EPI>
__global__ __launch_bounds__(256, 2)
void gemm_kernel(const float* __restrict__ A, const float* __restrict__ B,
                 const float* __restrict__ bias, const float* __restrict__ resid,
                 float* __restrict__ C, int K, int ldn,
                 const float* __restrict__ qw, const float* __restrict__ qb,
                 const float* __restrict__ kw, const float* __restrict__ kb)
{
    constexpr int KT  = 64;
    constexpr int RPT = BM / 8;
    constexpr int LDA = BM + 2;
    extern __shared__ __align__(16) char sm_raw[];
    u64* B2 = (u64*)sm_raw;        // [KT][128]  packed (c, c+128)
    u64* A2 = B2 + KT * 128;       // [KT][LDA]  packed (a, a), kk-major

    const int t   = threadIdx.x;
    const int txd = t & 31;
    const int tyi = t >> 5;
    const int m0  = blockIdx.x * BM;
    const int n0  = blockIdx.y * 256;

    u64 acc[RPT][4];
    #pragma unroll
    for (int r = 0; r < RPT; r++)
        #pragma unroll
        for (int d = 0; d < 4; d++) acc[r][d] = 0ULL;

    for (int k0 = 0; k0 < K; k0 += KT) {
        __syncthreads();
        #pragma unroll
        for (int r = 0; r < (KT * 128) / 256; r++) {
            int idx = t + r * 256;
            int j = idx >> 7, c = idx & 127;
            const float* br = B + (size_t)(k0 + j) * ldn + n0;
            B2[j * 128 + c] = pack2(br[c], br[c + 128]);
        }
        #pragma unroll
        for (int r = 0; r < (BM * KT) / 256; r++) {
            int idx = t + r * 256;
            int kk = idx & 63, mi = idx >> 6;
            float a = A[(size_t)(m0 + mi) * K + k0 + kk];
            A2[kk * LDA + mi] = pack2(a, a);
        }
        __syncthreads();
        #pragma unroll 8
        for (int kk = 0; kk < KT; kk++) {
            ulonglong2 v01 = *(const ulonglong2*)(B2 + kk * 128 + 2 * txd);
            ulonglong2 v23 = *(const ulonglong2*)(B2 + kk * 128 + 64 + 2 * txd);
            #pragma unroll
            for (int rr = 0; rr < RPT / 2; rr++) {
                ulonglong2 aa = *(const ulonglong2*)(A2 + kk * LDA + tyi * RPT + 2 * rr);
                fma2(acc[2*rr][0], aa.x, v01.x);
                fma2(acc[2*rr][1], aa.x, v01.y);
                fma2(acc[2*rr][2], aa.x, v23.x);
                fma2(acc[2*rr][3], aa.x, v23.y);
                fma2(acc[2*rr+1][0], aa.y, v01.x);
                fma2(acc[2*rr+1][1], aa.y, v01.y);
                fma2(acc[2*rr+1][2], aa.y, v23.x);
                fma2(acc[2*rr+1][3], aa.y, v23.y);
            }
        }
    }

    const int cA = n0 + 2 * txd;
    const int cB = cA + 128;
    const int cC = n0 + 64 + 2 * txd;
    const int cD = cC + 128;
    float bA0 = bias[cA], bA1 = bias[cA + 1];
    float bB0 = bias[cB], bB1 = bias[cB + 1];
    float bC0 = bias[cC], bC1 = bias[cC + 1];
    float bD0 = bias[cD], bD1 = bias[cD + 1];

    float2 qwA, qwB, qwC, qwD, kwA, kwB, kwC, kwD;
    float qbv = 0.f, kbv = 0.f;
    if (EPI == 2) {
        qwA = *(const float2*)(qw + 2 * txd);
        qwB = *(const float2*)(qw + 128 + 2 * txd);
        qwC = *(const float2*)(qw + 64 + 2 * txd);
        qwD = *(const float2*)(qw + 192 + 2 * txd);
        kwA = *(const float2*)(kw + 2 * txd);
        kwB = *(const float2*)(kw + 128 + 2 * txd);
        kwC = *(const float2*)(kw + 64 + 2 * txd);
        kwD = *(const float2*)(kw + 192 + 2 * txd);
        qbv = qb[0]; kbv = kb[0];
    }

    #pragma unroll
    for (int r = 0; r < RPT; r++) {
        int m = m0 + tyi * RPT + r;
        float a0, a1, b0, b1, c0, c1, d0, d1;
        unpack2(acc[r][0], a0, a1);
        unpack2(acc[r][1], b0, b1);
        unpack2(acc[r][2], c0, c1);
        unpack2(acc[r][3], d0, d1);
        float xA0 = a0 + bA0, xA1 = b0 + bA1;
        float xB0 = a1 + bB0, xB1 = b1 + bB1;
        float xC0 = c0 + bC0, xC1 = d0 + bC1;
        float xD0 = c1 + bD0, xD1 = d1 + bD1;
        float* crow = C + (size_t)m * ldn;
        if (EPI == 1) {
            const float* rrow = resid + (size_t)m * ldn;
            float2 rA = *(const float2*)(rrow + cA);
            float2 rB = *(const float2*)(rrow + cB);
            float2 rC = *(const float2*)(rrow + cC);
            float2 rD = *(const float2*)(rrow + cD);
            xA0 = 1.0f / (1.0f + expf(-(xA0 + rA.x)));
            xA1 = 1.0f / (1.0f + expf(-(xA1 + rA.y)));
            xB0 = 1.0f / (1.0f + expf(-(xB0 + rB.x)));
            xB1 = 1.0f / (1.0f + expf(-(xB1 + rB.y)));
            xC0 = 1.0f / (1.0f + expf(-(xC0 + rC.x)));
            xC1 = 1.0f / (1.0f + expf(-(xC1 + rC.y)));
            xD0 = 1.0f / (1.0f + expf(-(xD0 + rD.x)));
            xD1 = 1.0f / (1.0f + expf(-(xD1 + rD.y)));
        }
        *(float2*)(crow + cA) = make_float2(xA0, xA1);
        *(float2*)(crow + cB) = make_float2(xB0, xB1);
        *(float2*)(crow + cC) = make_float2(xC0, xC1);
        *(float2*)(crow + cD) = make_float2(xD0, xD1);

        if (EPI == 2) {
            float sq = xA0 * qwA.x + xA1 * qwA.y + xB0 * qwB.x + xB1 * qwB.y
                     + xC0 * qwC.x + xC1 * qwC.y + xD0 * qwD.x + xD1 * qwD.y;
            float sk = xA0 * kwA.x + xA1 * kwA.y + xB0 * kwB.x + xB1 * kwB.y
                     + xC0 * kwC.x + xC1 * kwC.y + xD0 * kwD.x + xD1 * kwD.y;
            #pragma unroll
            for (int o = 16; o > 0; o >>= 1) {
                sq += __shfl_down_sync(0xffffffffu, sq, o);
                sk += __shfl_down_sync(0xffffffffu, sk, o);
            }
            if (txd == 0) {
                int b = m >> 10, n = m & 1023;
                int bh = b * HEADSV + blockIdx.y;
                g_qv[bh * NN + n] = sq + qbv;
                g_kv[bh * NN + n] = sk + kbv;
            }
        }
    }
}

// ============================================================================
// Per-head factored-exp side tables (softmax shift-invariant; products <= 1):
//   m_i = leaky(q_i + kmax); writes g_qac=(q, e^{q-m}, e^{.01q-m}) and
//   g_kbd=(k, e^k, e^{.01k}).
//   exp(leaky(q_i+k_j) - m_i) = (q_i+k_j>=0) ? A_i*B_j : C_i*D_j
// ============================================================================
__global__ void abcd_kernel()
{
    __shared__ float red[256];
    int bh = blockIdx.x, t = threadIdx.x;
    const float* kv = g_kv + bh * NN;
    float m = -1e30f;
    for (int n = t; n < NN; n += 256) m = fmaxf(m, kv[n]);
    red[t] = m; __syncthreads();
    for (int s = 128; s > 0; s >>= 1) {
        if (t < s) red[t] = fmaxf(red[t], red[t + s]);
        __syncthreads();
    }
    float kmax = red[0];
    const float* qv = g_qv + bh * NN;
    for (int n = t; n < NN; n += 256) {
        float q = qv[n], k = kv[n];
        float xm = q + kmax;
        float mi = (xm >= 0.f) ? xm : 0.01f * xm;
        g_qac[bh * NN + n] = make_float4(q, expf(q - mi), expf(0.01f * q - mi), 0.f);
        g_kbd[bh * NN + n] = make_float4(k, expf(k), expf(0.01f * k), 0.f);
    }
}

// ============================================================================
// Sparse attention, cp.async triple-buffered:
// CTA = (bh, 64-row i-tile), 8 warps, warp = 8 rows x 256 d (acc[8][4] f32x2).
// 32 j-tiles of 32 rows; V tile (32 KB), kbd tile, mask tile staged with
// cp.async 2 tiles ahead. Edge loop processes rows in PAIRS (two independent
// bitmask chains interleaved) to halve exposed LDS latency.
//   p = (q_i+k_j>=0) ? A_i*B_j : C_i*D_j  (masked entries exactly 0, matching
//   the fp32 reference where exp(~-1e7) underflows); l_i += p; O_i += p*V_j.
// ============================================================================
__global__ __launch_bounds__(256, 2)
void attn_kernel()
{
    extern __shared__ __align__(16) char sm_raw[];
    float*    Vb  = (float*)sm_raw;                          // [3][32*256]
    float4*   Kb  = (float4*)(sm_raw + 3 * 32768);           // [3][32]
    unsigned* Mb  = (unsigned*)(sm_raw + 3 * 32768 + 3*512); // [3][64]
    float4*   QAC = (float4*)(sm_raw + 3 * 32768 + 3*512 + 3*256); // [64]

    const int t   = threadIdx.x;
    const int txd = t & 31;
    const int tyi = t >> 5;
    const int bh  = blockIdx.x;
    const int b   = bh >> 3, h = bh & 7;
    const int i0  = blockIdx.y * 64;
    const int bi0 = b * NN + i0;

    const unsigned sV0 = smem_u32(Vb);
    const unsigned sK0 = smem_u32(Kb);
    const unsigned sM0 = smem_u32(Mb);

    // one-time per-row (q, A, C) into smem
    if (t < 64) QAC[t] = g_qac[bh * NN + i0 + t];

    u64 acc[8][4];
    #pragma unroll
    for (int r = 0; r < 8; r++)
        #pragma unroll
        for (int d = 0; d < 4; d++) acc[r][d] = 0ULL;
    float lr[8];
    #pragma unroll
    for (int r = 0; r < 8; r++) lr[r] = 0.f;

    const float*  vsrc = g_fp + ((size_t)b * NN * 2048 + h * 256);
    const float4* ksrc = g_kbd + bh * NN;

    // ---- stage tile jt into slot s (all threads; per-thread commit) ----
    auto stage = [&](int jt, int s) {
        int j0 = jt * 32;
        unsigned sV = sV0 + s * 32768;
        #pragma unroll
        for (int i = 0; i < 8; i++) {
            int idx = t + i * 256;
            int row = idx >> 6, c = idx & 63;
            cpasync16(sV + row * 1024 + c * 16, vsrc + (size_t)(j0 + row) * 2048 + c * 4);
        }
        if (t < 32) cpasync16(sK0 + s * 512 + t * 16, ksrc + j0 + t);
        if (t < 16) cpasync16(sM0 + s * 256 + t * 16, g_m32 + jt * 8192 + bi0 + t * 4);
        CP_COMMIT();
    };

    stage(0, 0);
    stage(1, 1);

    int sl = 0;        // processing slot
    for (int jt = 0; jt < 32; jt++) {
        if (jt >= 30) CP_WAIT0(); else CP_WAIT1();
        __syncthreads();                    // tile jt visible; all done with jt-1
        if (jt + 2 < 32) stage(jt + 2, (sl + 2 >= 3) ? sl - 1 : sl + 2);

        const float*    Vs = Vb + sl * 8192;
        const float4*   Ks = Kb + sl * 32;
        const unsigned* Ms = Mb + sl * 64;

        #pragma unroll
        for (int r = 0; r < 8; r += 2) {
            unsigned ma = Ms[tyi * 8 + r];
            unsigned mb = Ms[tyi * 8 + r + 1];
            if ((ma | mb) == 0u) continue;
            float4 qa = QAC[tyi * 8 + r];
            float4 qb = QAC[tyi * 8 + r + 1];
            while (ma | mb) {
                int ja = -1, jb = -1;
                if (ma) { ja = __ffs((int)ma) - 1; ma &= ma - 1; }
                if (mb) { jb = __ffs((int)mb) - 1; mb &= mb - 1; }
                if (ja >= 0) {
                    float4 kk = Ks[ja];
                    const float4* v4 = (const float4*)(Vs + ja * 256);
                    float4 va0 = v4[txd];
                    float4 va1 = v4[32 + txd];
                    float x = qa.x + kk.x;
                    float p = (x >= 0.f) ? qa.y * kk.y : qa.z * kk.z;
                    lr[r] += p;
                    u64 pp = pack2(p, p);
                    fma2(acc[r][0], pp, pack2(va0.x, va0.y));
                    fma2(acc[r][1], pp, pack2(va0.z, va0.w));
                    fma2(acc[r][2], pp, pack2(va1.x, va1.y));
                    fma2(acc[r][3], pp, pack2(va1.z, va1.w));
                }
                if (jb >= 0) {
                    float4 kk = Ks[jb];
                    const float4* v4 = (const float4*)(Vs + jb * 256);
                    float4 vb0 = v4[txd];
                    float4 vb1 = v4[32 + txd];
                    float x = qb.x + kk.x;
                    float p = (x >= 0.f) ? qb.y * kk.y : qb.z * kk.z;
                    lr[r + 1] += p;
                    u64 pp = pack2(p, p);
                    fma2(acc[r + 1][0], pp, pack2(vb0.x, vb0.y));
                    fma2(acc[r + 1][1], pp, pack2(vb0.z, vb0.w));
                    fma2(acc[r + 1][2], pp, pack2(vb1.x, vb1.y));
                    fma2(acc[r + 1][3], pp, pack2(vb1.z, vb1.w));
                }
            }
        }
        sl = (sl == 2) ? 0 : sl + 1;
    }

    #pragma unroll
    for (int r = 0; r < 8; r++) {
        float l = lr[r];
        float inv = (l > 0.f) ? 1.0f / l : 0.f;
        float* orow = g_attn + (size_t)(b * NN + i0 + tyi * 8 + r) * 2048 + h * 256;
        float a0, a1, b0, b1, c0, c1, d0, d1;
        unpack2(acc[r][0], a0, a1);   // cols 4txd, 4txd+1
        unpack2(acc[r][1], b0, b1);   // cols 4txd+2, 4txd+3
        unpack2(acc[r][2], c0, c1);   // cols 128+4txd, +1
        unpack2(acc[r][3], d0, d1);   // cols 128+4txd+2, +3
        *(float4*)(orow + 4 * txd)       = make_float4(a0*inv, a1*inv, b0*inv, b1*inv);
        *(float4*)(orow + 128 + 4 * txd) = make_float4(c0*inv, c1*inv, d0*inv, d1*inv);
    }
}

// ============================================================================
extern "C" void kernel_launch(void* const* d_in, const int* in_sizes, int n_in,
                              void* d_out, int out_size)
{
    const float* feats = (const float*)d_in[0];
    const float* adj   = (const float*)d_in[1];
    const float* fc_w  = (const float*)d_in[2];
    const float* fc_b  = (const float*)d_in[3];
    const float* q_w   = (const float*)d_in[4];
    const float* q_b   = (const float*)d_in[5];
    const float* k_w   = (const float*)d_in[6];
    const float* k_b   = (const float*)d_in[7];
    const float* fp_w  = (const float*)d_in[8];
    const float* fp_b  = (const float*)d_in[9];
    float* out = (float*)d_out;

    const int smem_g1 = (64 * 128 + 64 * 66) * 8;              // 99328
    const int smem_g3 = (64 * 128 + 64 * 34) * 8;              // 82944
    const int smem_at = 3 * 32768 + 3 * 512 + 3 * 256 + 1024;  // 101632

    cudaFuncSetAttribute(gemm_kernel<64, 2>, cudaFuncAttributeMaxDynamicSharedMemorySize, smem_g1);
    cudaFuncSetAttribute(gemm_kernel<32, 1>, cudaFuncAttributeMaxDynamicSharedMemorySize, smem_g3);
    cudaFuncSetAttribute(attn_kernel,        cudaFuncAttributeMaxDynamicSharedMemorySize, smem_at);

    float* fp_buf = nullptr;
    float* at_buf = nullptr;
    cudaGetSymbolAddress((void**)&fp_buf, g_fp);
    cudaGetSymbolAddress((void**)&at_buf, g_attn);

    // 1) adjacency bitmasks (shared across heads, transposed layout)
    mask_kernel<<<1024, 256>>>(adj);

    // 2) feat_proj = feats @ fc_w + fc_b, with fused q/k scalar projections
    gemm_kernel<64, 2><<<dim3(8192 / 64, 2048 / 256), 256, smem_g1>>>(
        feats, fc_w, fc_b, nullptr, fp_buf, 256, 2048, q_w, q_b, k_w, k_b);

    // 3) per-head kmax + factored exp side tables
    abcd_kernel<<<64, 256>>>();

    // 4) sparse masked-softmax attention (cp.async pipelined bitmask gather)
    attn_kernel<<<dim3(64, 16), 256, smem_at>>>();

    // 5) out = sigmoid(attn_out @ fp_w + fp_b + feats)
    gemm_kernel<32, 1><<<dim3(8192 / 32, 1), 256, smem_g3>>>(
        at_buf, fp_w, fp_b, feats, out, 2048, 256,
        nullptr, nullptr, nullptr, nullptr);
}

// round 11
// speedup vs baseline: 2.0117x; 1.5313x over previous
#include <cuda_runtime.h>
#include <math.h>

#define DIMV 256
#define HEADSV 8
#define BSZ 8
#define NN 1024

typedef unsigned long long u64;

// ---- scratch (device globals: no allocations allowed) ----
__device__ float g_fp[BSZ * NN * DIMV * HEADSV];    // 64 MB  feat_proj [8192][2048]
__device__ float g_attn[BSZ * NN * DIMV * HEADSV];  // 64 MB  attn out  [8192][2048]
__device__ float g_qv[BSZ * HEADSV * NN];
__device__ float g_kv[BSZ * HEADSV * NN];
__device__ float4 g_kbd[BSZ * HEADSV * NN];         // (k, B=e^k, D=e^{.01k}, 0)
__device__ float4 g_qac[BSZ * HEADSV * NN];         // (q, A=e^{q-m}, C=e^{.01q-m}, 0)
// adjacency bitmasks, transposed: g_m32[jt*8192 + (b*1024+i)] = 32 j-bits (1 MB)
__device__ unsigned g_m32[32 * BSZ * NN];

// ---- packed f32x2 helpers (sm_103a) ----
__device__ __forceinline__ u64 pack2(float x, float y) {
    u64 r; asm("mov.b64 %0, {%1, %2};" : "=l"(r) : "f"(x), "f"(y)); return r;
}
__device__ __forceinline__ void unpack2(u64 v, float &x, float &y) {
    asm("mov.b64 {%0, %1}, %2;" : "=f"(x), "=f"(y) : "l"(v));
}
__device__ __forceinline__ void fma2(u64 &d, u64 a, u64 b) {
    asm("fma.rn.f32x2 %0, %1, %2, %0;" : "+l"(d) : "l"(a), "l"(b));
}
// ---- cp.async helpers ----
__device__ __forceinline__ void cpasync16(unsigned s, const void* g) {
    asm volatile("cp.async.ca.shared.global [%0], [%1], 16;" :: "r"(s), "l"(g));
}
#define CP_COMMIT() asm volatile("cp.async.commit_group;" ::: "memory")
#define CP_WAIT1()  asm volatile("cp.async.wait_group 1;" ::: "memory")
#define CP_WAIT0()  asm volatile("cp.async.wait_group 0;" ::: "memory")

__device__ __forceinline__ unsigned smem_u32(const void* p) {
    unsigned a;
    asm("{ .reg .u64 t; cvta.to.shared.u64 t, %1; cvt.u32.u64 %0, t; }"
        : "=r"(a) : "l"(p));
    return a;
}
// ---- tf32 mma helpers ----
__device__ __forceinline__ unsigned cvt_tf32(float x) {
    unsigned r; asm("cvt.rna.tf32.f32 %0, %1;" : "=r"(r) : "f"(x)); return r;
}
__device__ __forceinline__ void mma1688(float* c, const unsigned* a, const unsigned* b) {
    asm("mma.sync.aligned.m16n8k8.row.col.f32.tf32.tf32.f32 "
        "{%0,%1,%2,%3}, {%4,%5,%6,%7}, {%8,%9}, {%0,%1,%2,%3};"
        : "+f"(c[0]), "+f"(c[1]), "+f"(c[2]), "+f"(c[3])
        : "r"(a[0]), "r"(a[1]), "r"(a[2]), "r"(a[3]), "r"(b[0]), "r"(b[1]));
}

// ============================================================================
// Adjacency -> transposed 32-bit masks: warp per row, 32 j-tiles of 32 bits.
// ============================================================================
__global__ void mask_kernel(const float* __restrict__ adj)
{
    int bi   = blockIdx.x * 8 + (threadIdx.x >> 5);   // 0..8191
    int lane = threadIdx.x & 31;
    const float* row = adj + (size_t)bi * 1024;
    #pragma unroll
    for (int jt = 0; jt < 32; jt++) {
        unsigned mm = __ballot_sync(0xffffffffu, row[jt * 32 + lane] != 0.f);
        if (lane == 0) g_m32[jt * 8192 + bi] = mm;
    }
}

// ============================================================================
// tf32 tensor-core GEMM: C[M][128-window] = A[M][K] @ B[K][ldn] (+bias, epi)
// CTA tile 128x128, 8 warps (2x4), warp tile 64x32 = 4x4 m16n8k8 mma.
// K-chunk 32, cp.async double-buffered. smem: A[128][36] (m-major, pad 36),
// B[32][136] (k-major, pad 136) -> conflict-free fragment LDS.
// Fragments cvt.rna.tf32'd in registers (issue slots spare; tensor pipe binds).
// EPI 0: +bias.  EPI 1: +bias +resid, sigmoid.
// ============================================================================
template<int EPI>
__global__ __launch_bounds__(256, 2)
void mma_gemm(const float* __restrict__ A, const float* __restrict__ B,
              const float* __restrict__ bias, const float* __restrict__ resid,
              float* __restrict__ C, int K, int ldn)
{
    extern __shared__ __align__(16) float smf[];
    float* As = smf;                  // [2][128][36]
    float* Bs = smf + 2 * 128 * 36;   // [2][32][136]
    const unsigned sA0 = smem_u32(As);
    const unsigned sB0 = smem_u32(Bs);

    const int t    = threadIdx.x;
    const int lane = t & 31;
    const int wid  = t >> 5;
    const int wm   = (wid >> 2) * 64;   // warp m-offset in tile
    const int wn   = (wid & 3) * 32;    // warp n-offset in tile
    const int m0   = blockIdx.x * 128;
    const int n0   = blockIdx.y * 128;
    const int gq   = lane >> 2;         // groupID
    const int tq   = lane & 3;          // threadID in group

    float cacc[4][4][4];
    #pragma unroll
    for (int mi = 0; mi < 4; mi++)
        #pragma unroll
        for (int ni = 0; ni < 4; ni++)
            #pragma unroll
            for (int r = 0; r < 4; r++) cacc[mi][ni][r] = 0.f;

    auto stage = [&](int kc, int buf) {
        #pragma unroll
        for (int i = 0; i < 4; i++) {       // A: 128 rows x 32 floats
            int idx = t + i * 256;
            int row = idx >> 3, ch = idx & 7;
            cpasync16(sA0 + (buf * 4608 + row * 36 + ch * 4) * 4,
                      A + (size_t)(m0 + row) * K + kc + ch * 4);
        }
        #pragma unroll
        for (int i = 0; i < 4; i++) {       // B: 32 rows x 128 floats
            int idx = t + i * 256;
            int row = idx >> 5, ch = idx & 31;
            cpasync16(sB0 + (buf * 4352 + row * 136 + ch * 4) * 4,
                      B + (size_t)(kc + row) * ldn + n0 + ch * 4);
        }
        CP_COMMIT();
    };

    const int nch = K / 32;
    stage(0, 0);
    for (int c = 0; c < nch; c++) {
        CP_WAIT0();
        __syncthreads();                    // chunk c visible; buffer (c+1)&1 free
        if (c + 1 < nch) stage((c + 1) * 32, (c + 1) & 1);

        const float* As_ = As + (c & 1) * 4608;
        const float* Bs_ = Bs + (c & 1) * 4352;

        #pragma unroll
        for (int ks = 0; ks < 4; ks++) {
            int kk = ks * 8;
            unsigned af[4][4], bf[4][2];
            #pragma unroll
            for (int mi = 0; mi < 4; mi++) {
                int mr = wm + mi * 16 + gq;
                af[mi][0] = cvt_tf32(As_[mr * 36 + kk + tq]);
                af[mi][1] = cvt_tf32(As_[(mr + 8) * 36 + kk + tq]);
                af[mi][2] = cvt_tf32(As_[mr * 36 + kk + 4 + tq]);
                af[mi][3] = cvt_tf32(As_[(mr + 8) * 36 + kk + 4 + tq]);
            }
            #pragma unroll
            for (int ni = 0; ni < 4; ni++) {
                int nc = wn + ni * 8 + gq;
                bf[ni][0] = cvt_tf32(Bs_[(kk + tq) * 136 + nc]);
                bf[ni][1] = cvt_tf32(Bs_[(kk + 4 + tq) * 136 + nc]);
            }
            #pragma unroll
            for (int mi = 0; mi < 4; mi++)
                #pragma unroll
                for (int ni = 0; ni < 4; ni++)
                    mma1688(cacc[mi][ni], af[mi], bf[ni]);
        }
        __syncthreads();                    // all warps done with buffer c&1
    }

    // epilogue
    #pragma unroll
    for (int mi = 0; mi < 4; mi++) {
        int row0 = m0 + wm + mi * 16 + gq;
        #pragma unroll
        for (int ni = 0; ni < 4; ni++) {
            int col = n0 + wn + ni * 8 + 2 * tq;
            float b0v = bias[col], b1v = bias[col + 1];
            float x0 = cacc[mi][ni][0] + b0v;
            float x1 = cacc[mi][ni][1] + b1v;
            float x2 = cacc[mi][ni][2] + b0v;
            float x3 = cacc[mi][ni][3] + b1v;
            if (EPI == 1) {
                const float* r0 = resid + (size_t)row0 * ldn + col;
                const float* r1 = resid + (size_t)(row0 + 8) * ldn + col;
                x0 = 1.0f / (1.0f + expf(-(x0 + r0[0])));
                x1 = 1.0f / (1.0f + expf(-(x1 + r0[1])));
                x2 = 1.0f / (1.0f + expf(-(x2 + r1[0])));
                x3 = 1.0f / (1.0f + expf(-(x3 + r1[1])));
            }
            *(float2*)(C + (size_t)row0 * ldn + col)       = make_float2(x0, x1);
            *(float2*)(C + (size_t)(row0 + 8) * ldn + col) = make_float2(x2, x3);
        }
    }
}

// ============================================================================
// q/k scalar projections: one warp per (row, head), reading feat_proj.
// ============================================================================
__global__ void qk_kernel(const float* __restrict__ qw, const float* __restrict__ qb,
                          const float* __restrict__ kw, const float* __restrict__ kb)
{
    int r = blockIdx.x;               // 0..8191 = b*1024+n
    int t = threadIdx.x;
    int h = t >> 5, lane = t & 31;
    const float* row = g_fp + (size_t)r * 2048 + h * 256;
    float sq = 0.f, sk = 0.f;
    #pragma unroll
    for (int i = 0; i < 8; i++) {
        float f = row[lane + 32 * i];
        sq += f * qw[lane + 32 * i];
        sk += f * kw[lane + 32 * i];
    }
    #pragma unroll
    for (int o = 16; o > 0; o >>= 1) {
        sq += __shfl_down_sync(0xffffffffu, sq, o);
        sk += __shfl_down_sync(0xffffffffu, sk, o);
    }
    if (lane == 0) {
        int b = r >> 10, n = r & 1023;
        int bh = b * HEADSV + h;
        g_qv[bh * NN + n] = sq + qb[0];
        g_kv[bh * NN + n] = sk + kb[0];
    }
}

// ============================================================================
// Per-head factored-exp side tables (softmax shift-invariant; products <= 1):
//   m_i = leaky(q_i + kmax); g_qac=(q, e^{q-m}, e^{.01q-m}), g_kbd=(k, e^k, e^{.01k})
//   exp(leaky(q_i+k_j) - m_i) = (q_i+k_j>=0) ? A_i*B_j : C_i*D_j
// ============================================================================
__global__ void abcd_kernel()
{
    __shared__ float red[256];
    int bh = blockIdx.x, t = threadIdx.x;
    const float* kv = g_kv + bh * NN;
    float m = -1e30f;
    for (int n = t; n < NN; n += 256) m = fmaxf(m, kv[n]);
    red[t] = m; __syncthreads();
    for (int s = 128; s > 0; s >>= 1) {
        if (t < s) red[t] = fmaxf(red[t], red[t + s]);
        __syncthreads();
    }
    float kmax = red[0];
    const float* qv = g_qv + bh * NN;
    for (int n = t; n < NN; n += 256) {
        float q = qv[n], k = kv[n];
        float xm = q + kmax;
        float mi = (xm >= 0.f) ? xm : 0.01f * xm;
        g_qac[bh * NN + n] = make_float4(q, expf(q - mi), expf(0.01f * q - mi), 0.f);
        g_kbd[bh * NN + n] = make_float4(k, expf(k), expf(0.01f * k), 0.f);
    }
}

// ============================================================================
// Sparse attention, cp.async triple-buffered (verified R9 version):
// CTA = (bh, 64-row i-tile), 8 warps, warp = 8 rows x 256 d (acc[8][4] f32x2).
// 32 j-tiles of 32 rows; V/kbd/mask tiles staged 2 ahead. Row-pair interleaved
// bitmask edge chains.  p = (q_i+k_j>=0) ? A_i*B_j : C_i*D_j (masked entries
// exactly 0, matching fp32 underflow of exp(~-1e7)); l += p; O += p*V.
// ============================================================================
__global__ __launch_bounds__(256, 2)
void attn_kernel()
{
    extern __shared__ __align__(16) char sm_raw[];
    float*    Vb  = (float*)sm_raw;                          // [3][32*256]
    float4*   Kb  = (float4*)(sm_raw + 3 * 32768);           // [3][32]
    unsigned* Mb  = (unsigned*)(sm_raw + 3 * 32768 + 3*512); // [3][64]
    float4*   QAC = (float4*)(sm_raw + 3 * 32768 + 3*512 + 3*256); // [64]

    const int t   = threadIdx.x;
    const int txd = t & 31;
    const int tyi = t >> 5;
    const int bh  = blockIdx.x;
    const int b   = bh >> 3, h = bh & 7;
    const int i0  = blockIdx.y * 64;
    const int bi0 = b * NN + i0;

    const unsigned sV0 = smem_u32(Vb);
    const unsigned sK0 = smem_u32(Kb);
    const unsigned sM0 = smem_u32(Mb);

    if (t < 64) QAC[t] = g_qac[bh * NN + i0 + t];

    u64 acc[8][4];
    #pragma unroll
    for (int r = 0; r < 8; r++)
        #pragma unroll
        for (int d = 0; d < 4; d++) acc[r][d] = 0ULL;
    float lr[8];
    #pragma unroll
    for (int r = 0; r < 8; r++) lr[r] = 0.f;

    const float*  vsrc = g_fp + ((size_t)b * NN * 2048 + h * 256);
    const float4* ksrc = g_kbd + bh * NN;

    auto stage = [&](int jt, int s) {
        int j0 = jt * 32;
        unsigned sV = sV0 + s * 32768;
        #pragma unroll
        for (int i = 0; i < 8; i++) {
            int idx = t + i * 256;
            int row = idx >> 6, c = idx & 63;
            cpasync16(sV + row * 1024 + c * 16, vsrc + (size_t)(j0 + row) * 2048 + c * 4);
        }
        if (t < 32) cpasync16(sK0 + s * 512 + t * 16, ksrc + j0 + t);
        if (t < 16) cpasync16(sM0 + s * 256 + t * 16, g_m32 + jt * 8192 + bi0 + t * 4);
        CP_COMMIT();
    };

    stage(0, 0);
    stage(1, 1);

    int sl = 0;
    for (int jt = 0; jt < 32; jt++) {
        if (jt >= 30) CP_WAIT0(); else CP_WAIT1();
        __syncthreads();
        if (jt + 2 < 32) stage(jt + 2, (sl + 2 >= 3) ? sl - 1 : sl + 2);

        const float*    Vs = Vb + sl * 8192;
        const float4*   Ks = Kb + sl * 32;
        const unsigned* Ms = Mb + sl * 64;

        #pragma unroll
        for (int r = 0; r < 8; r += 2) {
            unsigned ma = Ms[tyi * 8 + r];
            unsigned mb = Ms[tyi * 8 + r + 1];
            if ((ma | mb) == 0u) continue;
            float4 qa = QAC[tyi * 8 + r];
            float4 qb = QAC[tyi * 8 + r + 1];
            while (ma | mb) {
                int ja = -1, jb = -1;
                if (ma) { ja = __ffs((int)ma) - 1; ma &= ma - 1; }
                if (mb) { jb = __ffs((int)mb) - 1; mb &= mb - 1; }
                if (ja >= 0) {
                    float4 kk = Ks[ja];
                    const float4* v4 = (const float4*)(Vs + ja * 256);
                    float4 va0 = v4[txd];
                    float4 va1 = v4[32 + txd];
                    float x = qa.x + kk.x;
                    float p = (x >= 0.f) ? qa.y * kk.y : qa.z * kk.z;
                    lr[r] += p;
                    u64 pp = pack2(p, p);
                    fma2(acc[r][0], pp, pack2(va0.x, va0.y));
                    fma2(acc[r][1], pp, pack2(va0.z, va0.w));
                    fma2(acc[r][2], pp, pack2(va1.x, va1.y));
                    fma2(acc[r][3], pp, pack2(va1.z, va1.w));
                }
                if (jb >= 0) {
                    float4 kk = Ks[jb];
                    const float4* v4 = (const float4*)(Vs + jb * 256);
                    float4 vb0 = v4[txd];
                    float4 vb1 = v4[32 + txd];
                    float x = qb.x + kk.x;
                    float p = (x >= 0.f) ? qb.y * kk.y : qb.z * kk.z;
                    lr[r + 1] += p;
                    u64 pp = pack2(p, p);
                    fma2(acc[r + 1][0], pp, pack2(vb0.x, vb0.y));
                    fma2(acc[r + 1][1], pp, pack2(vb0.z, vb0.w));
                    fma2(acc[r + 1][2], pp, pack2(vb1.x, vb1.y));
                    fma2(acc[r + 1][3], pp, pack2(vb1.z, vb1.w));
                }
            }
        }
        sl = (sl == 2) ? 0 : sl + 1;
    }

    #pragma unroll
    for (int r = 0; r < 8; r++) {
        float l = lr[r];
        float inv = (l > 0.f) ? 1.0f / l : 0.f;
        float* orow = g_attn + (size_t)(b * NN + i0 + tyi * 8 + r) * 2048 + h * 256;
        float a0, a1, b0, b1, c0, c1, d0, d1;
        unpack2(acc[r][0], a0, a1);
        unpack2(acc[r][1], b0, b1);
        unpack2(acc[r][2], c0, c1);
        unpack2(acc[r][3], d0, d1);
        *(float4*)(orow + 4 * txd)       = make_float4(a0*inv, a1*inv, b0*inv, b1*inv);
        *(float4*)(orow + 128 + 4 * txd) = make_float4(c0*inv, c1*inv, d0*inv, d1*inv);
    }
}

// ============================================================================
extern "C" void kernel_launch(void* const* d_in, const int* in_sizes, int n_in,
                              void* d_out, int out_size)
{
    const float* feats = (const float*)d_in[0];
    const float* adj   = (const float*)d_in[1];
    const float* fc_w  = (const float*)d_in[2];
    const float* fc_b  = (const float*)d_in[3];
    const float* q_w   = (const float*)d_in[4];
    const float* q_b   = (const float*)d_in[5];
    const float* k_w   = (const float*)d_in[6];
    const float* k_b   = (const float*)d_in[7];
    const float* fp_w  = (const float*)d_in[8];
    const float* fp_b  = (const float*)d_in[9];
    float* out = (float*)d_out;

    const int smem_mm = (2 * 128 * 36 + 2 * 32 * 136) * 4;    // 71680
    const int smem_at = 3 * 32768 + 3 * 512 + 3 * 256 + 1024; // 101632

    cudaFuncSetAttribute(mma_gemm<0>, cudaFuncAttributeMaxDynamicSharedMemorySize, smem_mm);
    cudaFuncSetAttribute(mma_gemm<1>, cudaFuncAttributeMaxDynamicSharedMemorySize, smem_mm);
    cudaFuncSetAttribute(attn_kernel, cudaFuncAttributeMaxDynamicSharedMemorySize, smem_at);

    float* fp_buf = nullptr;
    float* at_buf = nullptr;
    cudaGetSymbolAddress((void**)&fp_buf, g_fp);
    cudaGetSymbolAddress((void**)&at_buf, g_attn);

    // 1) adjacency bitmasks (shared across heads, transposed layout)
    mask_kernel<<<1024, 256>>>(adj);

    // 2) feat_proj = feats @ fc_w + fc_b   (tf32 tensor cores)
    mma_gemm<0><<<dim3(8192 / 128, 2048 / 128), 256, smem_mm>>>(
        feats, fc_w, fc_b, nullptr, fp_buf, 256, 2048);

    // 3) q/k scalar projections
    qk_kernel<<<8192, 256>>>(q_w, q_b, k_w, k_b);

    // 4) per-head kmax + factored exp side tables
    abcd_kernel<<<64, 256>>>();

    // 5) sparse masked-softmax attention (cp.async pipelined bitmask gather)
    attn_kernel<<<dim3(64, 16), 256, smem_at>>>();

    // 6) out = sigmoid(attn_out @ fp_w + fp_b + feats)   (tf32 tensor cores)
    mma_gemm<1><<<dim3(8192 / 128, 256 / 128), 256, smem_mm>>>(
        at_buf, fp_w, fp_b, feats, out, 2048, 256);
}

// round 13
// speedup vs baseline: 2.9045x; 1.4438x over previous
// Resubmission of round-12 kernel: bench infra failed ("GB300 container failed
// twice") before compile/run; no measurement was taken. Kernel unchanged.
#include <cuda_runtime.h>
#include <math.h>

#define DIMV 256
#define HEADSV 8
#define BSZ 8
#define NN 1024

typedef unsigned long long u64;

// ---- scratch (device globals: no allocations allowed) ----
__device__ float g_fp[BSZ * NN * DIMV * HEADSV];    // 64 MB  feat_proj [8192][2048]
__device__ float g_attn[BSZ * NN * DIMV * HEADSV];  // 64 MB  attn out  [8192][2048]
__device__ float g_qv[BSZ * HEADSV * NN];
__device__ float g_kv[BSZ * HEADSV * NN];
__device__ float4 g_kbd[BSZ * HEADSV * NN];         // (k, B=e^k, D=e^{.01k}, 0)
__device__ float4 g_qac[BSZ * HEADSV * NN];         // (q, A=e^{q-m}, C=e^{.01q-m}, 0)
// adjacency bitmasks, transposed: g_m32[jt*8192 + (b*1024+i)] = 32 j-bits (1 MB)
__device__ unsigned g_m32[32 * BSZ * NN];

// ---- cp.async helpers ----
__device__ __forceinline__ void cpasync16(unsigned s, const void* g) {
    asm volatile("cp.async.ca.shared.global [%0], [%1], 16;" :: "r"(s), "l"(g));
}
#define CP_COMMIT() asm volatile("cp.async.commit_group;" ::: "memory")
#define CP_WAIT1()  asm volatile("cp.async.wait_group 1;" ::: "memory")
#define CP_WAIT0()  asm volatile("cp.async.wait_group 0;" ::: "memory")

__device__ __forceinline__ unsigned smem_u32(const void* p) {
    unsigned a;
    asm("{ .reg .u64 t; cvta.to.shared.u64 t, %1; cvt.u32.u64 %0, t; }"
        : "=r"(a) : "l"(p));
    return a;
}
// ---- tf32 mma helpers ----
__device__ __forceinline__ unsigned cvt_tf32(float x) {
    unsigned r; asm("cvt.rna.tf32.f32 %0, %1;" : "=r"(r) : "f"(x)); return r;
}
__device__ __forceinline__ void mma1688(float* c, const unsigned* a, const unsigned* b) {
    asm("mma.sync.aligned.m16n8k8.row.col.f32.tf32.tf32.f32 "
        "{%0,%1,%2,%3}, {%4,%5,%6,%7}, {%8,%9}, {%0,%1,%2,%3};"
        : "+f"(c[0]), "+f"(c[1]), "+f"(c[2]), "+f"(c[3])
        : "r"(a[0]), "r"(a[1]), "r"(a[2]), "r"(a[3]), "r"(b[0]), "r"(b[1]));
}

// ============================================================================
// Adjacency -> transposed 32-bit masks: warp per row, 32 j-tiles of 32 bits.
// ============================================================================
__global__ void mask_kernel(const float* __restrict__ adj)
{
    int bi   = blockIdx.x * 8 + (threadIdx.x >> 5);   // 0..8191
    int lane = threadIdx.x & 31;
    const float* row = adj + (size_t)bi * 1024;
    #pragma unroll
    for (int jt = 0; jt < 32; jt++) {
        unsigned mm = __ballot_sync(0xffffffffu, row[jt * 32 + lane] != 0.f);
        if (lane == 0) g_m32[jt * 8192 + bi] = mm;
    }
}

// ============================================================================
// tf32 tensor-core GEMM (validated R11): C = A @ B (+bias, epi).
// CTA 128x128, 8 warps 64x32, K-chunk 32 double-buffered cp.async.
// ============================================================================
template<int EPI>
__global__ __launch_bounds__(256, 2)
void mma_gemm(const float* __restrict__ A, const float* __restrict__ B,
              const float* __restrict__ bias, const float* __restrict__ resid,
              float* __restrict__ C, int K, int ldn)
{
    extern __shared__ __align__(16) float smf[];
    float* As = smf;                  // [2][128][36]
    float* Bs = smf + 2 * 128 * 36;   // [2][32][136]
    const unsigned sA0 = smem_u32(As);
    const unsigned sB0 = smem_u32(Bs);

    const int t    = threadIdx.x;
    const int lane = t & 31;
    const int wid  = t >> 5;
    const int wm   = (wid >> 2) * 64;
    const int wn   = (wid & 3) * 32;
    const int m0   = blockIdx.x * 128;
    const int n0   = blockIdx.y * 128;
    const int gq   = lane >> 2;
    const int tq   = lane & 3;

    float cacc[4][4][4];
    #pragma unroll
    for (int mi = 0; mi < 4; mi++)
        #pragma unroll
        for (int ni = 0; ni < 4; ni++)
            #pragma unroll
            for (int r = 0; r < 4; r++) cacc[mi][ni][r] = 0.f;

    auto stage = [&](int kc, int buf) {
        #pragma unroll
        for (int i = 0; i < 4; i++) {
            int idx = t + i * 256;
            int row = idx >> 3, ch = idx & 7;
            cpasync16(sA0 + (buf * 4608 + row * 36 + ch * 4) * 4,
                      A + (size_t)(m0 + row) * K + kc + ch * 4);
        }
        #pragma unroll
        for (int i = 0; i < 4; i++) {
            int idx = t + i * 256;
            int row = idx >> 5, ch = idx & 31;
            cpasync16(sB0 + (buf * 4352 + row * 136 + ch * 4) * 4,
                      B + (size_t)(kc + row) * ldn + n0 + ch * 4);
        }
        CP_COMMIT();
    };

    const int nch = K / 32;
    stage(0, 0);
    for (int c = 0; c < nch; c++) {
        CP_WAIT0();
        __syncthreads();
        if (c + 1 < nch) stage((c + 1) * 32, (c + 1) & 1);

        const float* As_ = As + (c & 1) * 4608;
        const float* Bs_ = Bs + (c & 1) * 4352;

        #pragma unroll
        for (int ks = 0; ks < 4; ks++) {
            int kk = ks * 8;
            unsigned af[4][4], bf[4][2];
            #pragma unroll
            for (int mi = 0; mi < 4; mi++) {
                int mr = wm + mi * 16 + gq;
                af[mi][0] = cvt_tf32(As_[mr * 36 + kk + tq]);
                af[mi][1] = cvt_tf32(As_[(mr + 8) * 36 + kk + tq]);
                af[mi][2] = cvt_tf32(As_[mr * 36 + kk + 4 + tq]);
                af[mi][3] = cvt_tf32(As_[(mr + 8) * 36 + kk + 4 + tq]);
            }
            #pragma unroll
            for (int ni = 0; ni < 4; ni++) {
                int nc = wn + ni * 8 + gq;
                bf[ni][0] = cvt_tf32(Bs_[(kk + tq) * 136 + nc]);
                bf[ni][1] = cvt_tf32(Bs_[(kk + 4 + tq) * 136 + nc]);
            }
            #pragma unroll
            for (int mi = 0; mi < 4; mi++)
                #pragma unroll
                for (int ni = 0; ni < 4; ni++)
                    mma1688(cacc[mi][ni], af[mi], bf[ni]);
        }
        __syncthreads();
    }

    #pragma unroll
    for (int mi = 0; mi < 4; mi++) {
        int row0 = m0 + wm + mi * 16 + gq;
        #pragma unroll
        for (int ni = 0; ni < 4; ni++) {
            int col = n0 + wn + ni * 8 + 2 * tq;
            float b0v = bias[col], b1v = bias[col + 1];
            float x0 = cacc[mi][ni][0] + b0v;
            float x1 = cacc[mi][ni][1] + b1v;
            float x2 = cacc[mi][ni][2] + b0v;
            float x3 = cacc[mi][ni][3] + b1v;
            if (EPI == 1) {
                const float* r0 = resid + (size_t)row0 * ldn + col;
                const float* r1 = resid + (size_t)(row0 + 8) * ldn + col;
                x0 = 1.0f / (1.0f + expf(-(x0 + r0[0])));
                x1 = 1.0f / (1.0f + expf(-(x1 + r0[1])));
                x2 = 1.0f / (1.0f + expf(-(x2 + r1[0])));
                x3 = 1.0f / (1.0f + expf(-(x3 + r1[1])));
            }
            *(float2*)(C + (size_t)row0 * ldn + col)       = make_float2(x0, x1);
            *(float2*)(C + (size_t)(row0 + 8) * ldn + col) = make_float2(x2, x3);
        }
    }
}

// ============================================================================
// q/k scalar projections: one warp per (row, head), reading feat_proj.
// ============================================================================
__global__ void qk_kernel(const float* __restrict__ qw, const float* __restrict__ qb,
                          const float* __restrict__ kw, const float* __restrict__ kb)
{
    int r = blockIdx.x;
    int t = threadIdx.x;
    int h = t >> 5, lane = t & 31;
    const float* row = g_fp + (size_t)r * 2048 + h * 256;
    float sq = 0.f, sk = 0.f;
    #pragma unroll
    for (int i = 0; i < 8; i++) {
        float f = row[lane + 32 * i];
        sq += f * qw[lane + 32 * i];
        sk += f * kw[lane + 32 * i];
    }
    #pragma unroll
    for (int o = 16; o > 0; o >>= 1) {
        sq += __shfl_down_sync(0xffffffffu, sq, o);
        sk += __shfl_down_sync(0xffffffffu, sk, o);
    }
    if (lane == 0) {
        int b = r >> 10, n = r & 1023;
        int bh = b * HEADSV + h;
        g_qv[bh * NN + n] = sq + qb[0];
        g_kv[bh * NN + n] = sk + kb[0];
    }
}

// ============================================================================
// Per-head factored-exp side tables (softmax shift-invariant; products <= 1):
//   m_i = leaky(q_i + kmax); g_qac=(q, e^{q-m}, e^{.01q-m}), g_kbd=(k, e^k, e^{.01k})
//   exp(leaky(q_i+k_j) - m_i) = (q_i+k_j>=0) ? A_i*B_j : C_i*D_j
// ============================================================================
__global__ void abcd_kernel()
{
    __shared__ float red[256];
    int bh = blockIdx.x, t = threadIdx.x;
    const float* kv = g_kv + bh * NN;
    float m = -1e30f;
    for (int n = t; n < NN; n += 256) m = fmaxf(m, kv[n]);
    red[t] = m; __syncthreads();
    for (int s = 128; s > 0; s >>= 1) {
        if (t < s) red[t] = fmaxf(red[t], red[t + s]);
        __syncthreads();
    }
    float kmax = red[0];
    const float* qv = g_qv + bh * NN;
    for (int n = t; n < NN; n += 256) {
        float q = qv[n], k = kv[n];
        float xm = q + kmax;
        float mi = (xm >= 0.f) ? xm : 0.01f * xm;
        g_qac[bh * NN + n] = make_float4(q, expf(q - mi), expf(0.01f * q - mi), 0.f);
        g_kbd[bh * NN + n] = make_float4(k, expf(k), expf(0.01f * k), 0.f);
    }
}

// ============================================================================
// Tensor-core attention: CTA = (bh, 128-row i-tile), 8 warps (2m x 4n),
// warp tile 64x64 of the 128x256 output. Per 32-row j-tile (triple-buffered
// cp.async V/kbd/mask staging, R9 schedule):
//   1) build P[128][32] in smem: p = bit ? ((q+k>=0) ? A*B : C*D) : 0
//      (fp32 select; masked entries exactly 0, matching reference underflow),
//      row-sums l accumulated in fp32 registers during the build;
//   2) O += P @ V via m16n8k8 tf32 mma (fragment mapping validated in mma_gemm).
// Epilogue: O_row /= l_row.
// ============================================================================
__global__ __launch_bounds__(256, 1)
void attn_kernel()
{
    extern __shared__ __align__(16) char sm_raw[];
    float*    Vb   = (float*)sm_raw;                         // [3][32][264]
    float*    Pb   = Vb + 3 * 32 * 264;                      // [128][36]
    float4*   Kb   = (float4*)(Pb + 128 * 36);               // [3][32]
    unsigned* Mb   = (unsigned*)((char*)Kb + 3 * 512);       // [3][128]
    float*    l_sm = (float*)((char*)Mb + 3 * 512);          // [128]

    const int t    = threadIdx.x;
    const int lane = t & 31;
    const int wid  = t >> 5;
    const int wm   = (wid >> 2) * 64;
    const int wn   = (wid & 3) * 64;
    const int gq   = lane >> 2;
    const int tq   = lane & 3;
    const int bh   = blockIdx.x;
    const int b    = bh >> 3, h = bh & 7;
    const int i0   = blockIdx.y * 128;
    const int bi0  = b * NN + i0;

    const unsigned sV0 = smem_u32(Vb);
    const unsigned sK0 = smem_u32(Kb);
    const unsigned sM0 = smem_u32(Mb);

    // P-build ownership: rows prow+32i (i=0..3), col group pcg (4 cols)
    const int prow = t >> 3, pcg = t & 7;
    float pq[4], pA[4], pC[4], lr[4];
    #pragma unroll
    for (int i = 0; i < 4; i++) {
        float4 v = g_qac[bh * NN + i0 + prow + 32 * i];
        pq[i] = v.x; pA[i] = v.y; pC[i] = v.z; lr[i] = 0.f;
    }

    float cacc[4][8][4];
    #pragma unroll
    for (int mi = 0; mi < 4; mi++)
        #pragma unroll
        for (int ni = 0; ni < 8; ni++)
            #pragma unroll
            for (int r = 0; r < 4; r++) cacc[mi][ni][r] = 0.f;

    const float*  vsrc = g_fp + ((size_t)b * NN * 2048 + h * 256);
    const float4* ksrc = g_kbd + bh * NN;

    auto stage = [&](int jt, int s) {
        int j0 = jt * 32;
        unsigned sV = sV0 + s * 33792;
        #pragma unroll
        for (int i = 0; i < 8; i++) {
            int idx = t + i * 256;
            int row = idx >> 6, c = idx & 63;
            cpasync16(sV + row * 1056 + c * 16, vsrc + (size_t)(j0 + row) * 2048 + c * 4);
        }
        if (t < 32) {
            cpasync16(sK0 + s * 512 + t * 16, ksrc + j0 + t);
            cpasync16(sM0 + s * 512 + t * 16, g_m32 + jt * 8192 + bi0 + t * 4);
        }
        CP_COMMIT();
    };

    stage(0, 0);
    stage(1, 1);

    int sl = 0;
    for (int jt = 0; jt < 32; jt++) {
        if (jt >= 30) CP_WAIT0(); else CP_WAIT1();
        __syncthreads();                 // tile jt visible; prev mma done by all
        if (jt + 2 < 32) stage(jt + 2, (sl + 2 >= 3) ? sl - 1 : sl + 2);

        // ---- build P tile ----
        {
            const unsigned* Ms = Mb + sl * 128;
            const float4*   Ks = Kb + sl * 32;
            float4 kc0 = Ks[pcg * 4 + 0];
            float4 kc1 = Ks[pcg * 4 + 1];
            float4 kc2 = Ks[pcg * 4 + 2];
            float4 kc3 = Ks[pcg * 4 + 3];
            #pragma unroll
            for (int i = 0; i < 4; i++) {
                int row = prow + 32 * i;
                unsigned m = Ms[row];
                float q = pq[i], A = pA[i], C = pC[i];
                float x0 = q + kc0.x, x1 = q + kc1.x, x2 = q + kc2.x, x3 = q + kc3.x;
                float p0 = (x0 >= 0.f) ? A * kc0.y : C * kc0.z;
                float p1 = (x1 >= 0.f) ? A * kc1.y : C * kc1.z;
                float p2 = (x2 >= 0.f) ? A * kc2.y : C * kc2.z;
                float p3 = (x3 >= 0.f) ? A * kc3.y : C * kc3.z;
                p0 = (m & (1u << (pcg * 4 + 0))) ? p0 : 0.f;
                p1 = (m & (1u << (pcg * 4 + 1))) ? p1 : 0.f;
                p2 = (m & (1u << (pcg * 4 + 2))) ? p2 : 0.f;
                p3 = (m & (1u << (pcg * 4 + 3))) ? p3 : 0.f;
                lr[i] += (p0 + p1) + (p2 + p3);
                *(float4*)(Pb + row * 36 + pcg * 4) = make_float4(p0, p1, p2, p3);
            }
        }
        __syncthreads();                 // P visible

        // ---- O += P @ V ----
        const float* Vs = Vb + sl * 8448;
        #pragma unroll
        for (int ks = 0; ks < 4; ks++) {
            int kk = ks * 8;
            unsigned af[4][4], bf[8][2];
            #pragma unroll
            for (int mi = 0; mi < 4; mi++) {
                int mr = wm + mi * 16 + gq;
                af[mi][0] = cvt_tf32(Pb[mr * 36 + kk + tq]);
                af[mi][1] = cvt_tf32(Pb[(mr + 8) * 36 + kk + tq]);
                af[mi][2] = cvt_tf32(Pb[mr * 36 + kk + 4 + tq]);
                af[mi][3] = cvt_tf32(Pb[(mr + 8) * 36 + kk + 4 + tq]);
            }
            #pragma unroll
            for (int ni = 0; ni < 8; ni++) {
                int nc = wn + ni * 8 + gq;
                bf[ni][0] = cvt_tf32(Vs[(kk + tq) * 264 + nc]);
                bf[ni][1] = cvt_tf32(Vs[(kk + 4 + tq) * 264 + nc]);
            }
            #pragma unroll
            for (int mi = 0; mi < 4; mi++)
                #pragma unroll
                for (int ni = 0; ni < 8; ni++)
                    mma1688(cacc[mi][ni], af[mi], bf[ni]);
        }
        sl = (sl == 2) ? 0 : sl + 1;
    }

    // ---- l reduction: 8 col-group threads per row ----
    #pragma unroll
    for (int i = 0; i < 4; i++) {
        #pragma unroll
        for (int o = 4; o > 0; o >>= 1)
            lr[i] += __shfl_xor_sync(0xffffffffu, lr[i], o);
    }
    if (pcg == 0) {
        #pragma unroll
        for (int i = 0; i < 4; i++) l_sm[prow + 32 * i] = lr[i];
    }
    __syncthreads();

    // ---- epilogue: normalize and store ----
    #pragma unroll
    for (int mi = 0; mi < 4; mi++) {
        int row0 = wm + mi * 16 + gq;
        float l0 = l_sm[row0], l1 = l_sm[row0 + 8];
        float inv0 = (l0 > 0.f) ? 1.0f / l0 : 0.f;
        float inv1 = (l1 > 0.f) ? 1.0f / l1 : 0.f;
        float* o0 = g_attn + (size_t)(bi0 + row0) * 2048 + h * 256;
        float* o1 = g_attn + (size_t)(bi0 + row0 + 8) * 2048 + h * 256;
        #pragma unroll
        for (int ni = 0; ni < 8; ni++) {
            int col = wn + ni * 8 + 2 * tq;
            *(float2*)(o0 + col) = make_float2(cacc[mi][ni][0] * inv0, cacc[mi][ni][1] * inv0);
            *(float2*)(o1 + col) = make_float2(cacc[mi][ni][2] * inv1, cacc[mi][ni][3] * inv1);
        }
    }
}

// ============================================================================
extern "C" void kernel_launch(void* const* d_in, const int* in_sizes, int n_in,
                              void* d_out, int out_size)
{
    const float* feats = (const float*)d_in[0];
    const float* adj   = (const float*)d_in[1];
    const float* fc_w  = (const float*)d_in[2];
    const float* fc_b  = (const float*)d_in[3];
    const float* q_w   = (const float*)d_in[4];
    const float* q_b   = (const float*)d_in[5];
    const float* k_w   = (const float*)d_in[6];
    const float* k_b   = (const float*)d_in[7];
    const float* fp_w  = (const float*)d_in[8];
    const float* fp_b  = (const float*)d_in[9];
    float* out = (float*)d_out;

    const int smem_mm = (2 * 128 * 36 + 2 * 32 * 136) * 4;            // 71680
    const int smem_at = (3 * 32 * 264 + 128 * 36) * 4 + 3 * 512 + 3 * 512 + 512; // 123392

    cudaFuncSetAttribute(mma_gemm<0>, cudaFuncAttributeMaxDynamicSharedMemorySize, smem_mm);
    cudaFuncSetAttribute(mma_gemm<1>, cudaFuncAttributeMaxDynamicSharedMemorySize, smem_mm);
    cudaFuncSetAttribute(attn_kernel, cudaFuncAttributeMaxDynamicSharedMemorySize, smem_at);

    float* fp_buf = nullptr;
    float* at_buf = nullptr;
    cudaGetSymbolAddress((void**)&fp_buf, g_fp);
    cudaGetSymbolAddress((void**)&at_buf, g_attn);

    // 1) adjacency bitmasks (shared across heads, transposed layout)
    mask_kernel<<<1024, 256>>>(adj);

    // 2) feat_proj = feats @ fc_w + fc_b   (tf32 tensor cores)
    mma_gemm<0><<<dim3(8192 / 128, 2048 / 128), 256, smem_mm>>>(
        feats, fc_w, fc_b, nullptr, fp_buf, 256, 2048);

    // 3) q/k scalar projections
    qk_kernel<<<8192, 256>>>(q_w, q_b, k_w, k_b);

    // 4) per-head kmax + factored exp side tables
    abcd_kernel<<<64, 256>>>();

    // 5) masked-softmax attention, P@V on tensor cores
    attn_kernel<<<dim3(64, 8), 256, smem_at>>>();

    // 6) out = sigmoid(attn_out @ fp_w + fp_b + feats)   (tf32 tensor cores)
    mma_gemm<1><<<dim3(8192 / 128, 256 / 128), 256, smem_mm>>>(
        at_buf, fp_w, fp_b, feats, out, 2048, 256);
}

// round 16
// speedup vs baseline: 4.6159x; 1.5892x over previous
// Third submission attempt of the fp16-mma kernel. Rounds 14 and 15 both died
// broker-side ("GB300 container failed twice") before compile/run — same error
// string as round 12, which passed unchanged on resubmission. Kernel audited
// for hang/illegal-access mechanisms (none found); resubmitting unchanged.
#include <cuda_runtime.h>
#include <cuda_fp16.h>
#include <math.h>

#define DIMV 256
#define HEADSV 8
#define BSZ 8
#define NN 1024

typedef unsigned long long u64;

// ---- scratch (device globals: no allocations allowed) ----
__device__ float  g_fp[BSZ * NN * DIMV * HEADSV];     // 64 MB feat_proj fp32 (qk path)
__device__ __half g_fph[BSZ * NN * DIMV * HEADSV];    // 32 MB feat_proj fp16 (V source)
__device__ __half g_attn_h[BSZ * NN * DIMV * HEADSV]; // 32 MB attn out fp16 (GEMM3 A)
__device__ __half g_feats_h[BSZ * NN * DIMV];         //  4 MB feats fp16
__device__ __half g_fcw_h[DIMV * DIMV * HEADSV];      //  1 MB fc_w fp16
__device__ __half g_fpw_h[DIMV * HEADSV * DIMV];      //  1 MB fp_w fp16
__device__ float  g_qv[BSZ * HEADSV * NN];
__device__ float  g_kv[BSZ * HEADSV * NN];
__device__ float4 g_kbd[BSZ * HEADSV * NN];           // (k, B=e^k, D=e^{.01k}, 0)
__device__ float4 g_qac[BSZ * HEADSV * NN];           // (q, A=e^{q-m}, C=e^{.01q-m}, 0)
__device__ unsigned g_m32[32 * BSZ * NN];             // masks, transposed [jt][bi]

// ---- cp.async helpers ----
__device__ __forceinline__ void cpasync16(unsigned s, const void* g) {
    asm volatile("cp.async.ca.shared.global [%0], [%1], 16;" :: "r"(s), "l"(g));
}
#define CP_COMMIT() asm volatile("cp.async.commit_group;" ::: "memory")
#define CP_WAIT1()  asm volatile("cp.async.wait_group 1;" ::: "memory")
#define CP_WAIT0()  asm volatile("cp.async.wait_group 0;" ::: "memory")

__device__ __forceinline__ unsigned smem_u32(const void* p) {
    unsigned a;
    asm("{ .reg .u64 t; cvta.to.shared.u64 t, %1; cvt.u32.u64 %0, t; }"
        : "=r"(a) : "l"(p));
    return a;
}
// ---- fp16 mma helpers ----
__device__ __forceinline__ void mma_f16(float* c, const unsigned* a, const unsigned* b) {
    asm("mma.sync.aligned.m16n8k16.row.col.f32.f16.f16.f32 "
        "{%0,%1,%2,%3}, {%4,%5,%6,%7}, {%8,%9}, {%0,%1,%2,%3};"
        : "+f"(c[0]), "+f"(c[1]), "+f"(c[2]), "+f"(c[3])
        : "r"(a[0]), "r"(a[1]), "r"(a[2]), "r"(a[3]), "r"(b[0]), "r"(b[1]));
}
__device__ __forceinline__ void ldm_x4(unsigned* r, unsigned addr) {
    asm volatile("ldmatrix.sync.aligned.m8n8.x4.shared.b16 {%0,%1,%2,%3}, [%4];"
        : "=r"(r[0]), "=r"(r[1]), "=r"(r[2]), "=r"(r[3]) : "r"(addr));
}
__device__ __forceinline__ void ldm_x4_t(unsigned* r, unsigned addr) {
    asm volatile("ldmatrix.sync.aligned.m8n8.x4.trans.shared.b16 {%0,%1,%2,%3}, [%4];"
        : "=r"(r[0]), "=r"(r[1]), "=r"(r[2]), "=r"(r[3]) : "r"(addr));
}

// ============================================================================
// fp32 -> fp16 conversion (inputs; 4 elems/thread, exact-size grids)
// ============================================================================
__global__ void cvt_kernel(const float* __restrict__ s, __half* __restrict__ d)
{
    int i = (blockIdx.x * 256 + threadIdx.x) * 4;
    float4 v = *(const float4*)(s + i);
    __half2* o = (__half2*)(d + i);
    o[0] = __floats2half2_rn(v.x, v.y);
    o[1] = __floats2half2_rn(v.z, v.w);
}

// ============================================================================
// Adjacency -> transposed 32-bit masks: warp per row, 32 j-tiles of 32 bits.
// ============================================================================
__global__ void mask_kernel(const float* __restrict__ adj)
{
    int bi   = blockIdx.x * 8 + (threadIdx.x >> 5);
    int lane = threadIdx.x & 31;
    const float* row = adj + (size_t)bi * 1024;
    #pragma unroll
    for (int jt = 0; jt < 32; jt++) {
        unsigned mm = __ballot_sync(0xffffffffu, row[jt * 32 + lane] != 0.f);
        if (lane == 0) g_m32[jt * 8192 + bi] = mm;
    }
}

// ============================================================================
// fp16 tensor-core GEMM: C = A @ B (+bias, epi), fp32 accumulate.
// CTA 128x128, 8 warps 64x32, K-chunk 32 (2 x k16) double-buffered cp.async.
// smem fp16: A [128][40] (pitch 40 halfs), B [32][136]. Fragments via
// ldmatrix.x4 (A) / ldmatrix.x4.trans (B). C-fragment layout identical to the
// validated tf32 kernel's epilogue.
// EPI 0: +bias -> C fp32 and Ch fp16.  EPI 1: +bias +resid, sigmoid -> C fp32.
// ============================================================================
template<int EPI>
__global__ __launch_bounds__(256, 2)
void mma_gemm_h(const __half* __restrict__ A, const __half* __restrict__ B,
                const float* __restrict__ bias, const float* __restrict__ resid,
                float* __restrict__ C, __half* __restrict__ Ch, int K, int ldn)
{
    extern __shared__ __align__(16) __half smh[];
    __half* As = smh;                   // [2][128][40]
    __half* Bs = smh + 2 * 128 * 40;    // [2][32][136]
    const unsigned sA0 = smem_u32(As);
    const unsigned sB0 = smem_u32(Bs);

    const int t    = threadIdx.x;
    const int lane = t & 31;
    const int wid  = t >> 5;
    const int wm   = (wid >> 2) * 64;
    const int wn   = (wid & 3) * 32;
    const int m0   = blockIdx.x * 128;
    const int n0   = blockIdx.y * 128;
    const int gq   = lane >> 2;
    const int tq   = lane & 3;
    const int lr16 = lane & 15;         // ldmatrix row select
    const int lblk = (lane >> 4) << 3;  // ldmatrix 8-col block select

    float cacc[4][4][4];
    #pragma unroll
    for (int mi = 0; mi < 4; mi++)
        #pragma unroll
        for (int ni = 0; ni < 4; ni++)
            #pragma unroll
            for (int r = 0; r < 4; r++) cacc[mi][ni][r] = 0.f;

    auto stage = [&](int kc, int buf) {
        #pragma unroll
        for (int i = 0; i < 2; i++) {       // A: 128 rows x 32 halfs (4 chunks/row)
            int idx = t + i * 256;
            int row = idx >> 2, ch = idx & 3;
            cpasync16(sA0 + (buf * 5120 + row * 40 + ch * 8) * 2,
                      A + (size_t)(m0 + row) * K + kc + ch * 8);
        }
        #pragma unroll
        for (int i = 0; i < 2; i++) {       // B: 32 rows x 128 halfs (16 chunks/row)
            int idx = t + i * 256;
            int row = idx >> 4, ch = idx & 15;
            cpasync16(sB0 + (buf * 4352 + row * 136 + ch * 8) * 2,
                      B + (size_t)(kc + row) * ldn + n0 + ch * 8);
        }
        CP_COMMIT();
    };

    const int nch = K / 32;
    stage(0, 0);
    for (int c = 0; c < nch; c++) {
        CP_WAIT0();
        __syncthreads();
        if (c + 1 < nch) stage((c + 1) * 32, (c + 1) & 1);

        const unsigned sA_ = sA0 + (c & 1) * 5120 * 2;
        const unsigned sB_ = sB0 + (c & 1) * 4352 * 2;

        #pragma unroll
        for (int ks = 0; ks < 2; ks++) {
            int kk = ks * 16;
            unsigned af[4][4], bf[4][2];
            #pragma unroll
            for (int mi = 0; mi < 4; mi++) {
                int row = wm + mi * 16 + lr16;
                ldm_x4(af[mi], sA_ + (row * 40 + kk + lblk) * 2);
            }
            #pragma unroll
            for (int np = 0; np < 2; np++) {
                unsigned r4[4];
                ldm_x4_t(r4, sB_ + ((kk + lr16) * 136 + wn + np * 16 + lblk) * 2);
                bf[np * 2][0] = r4[0]; bf[np * 2][1] = r4[1];
                bf[np * 2 + 1][0] = r4[2]; bf[np * 2 + 1][1] = r4[3];
            }
            #pragma unroll
            for (int mi = 0; mi < 4; mi++)
                #pragma unroll
                for (int ni = 0; ni < 4; ni++)
                    mma_f16(cacc[mi][ni], af[mi], bf[ni]);
        }
        __syncthreads();
    }

    #pragma unroll
    for (int mi = 0; mi < 4; mi++) {
        int row0 = m0 + wm + mi * 16 + gq;
        #pragma unroll
        for (int ni = 0; ni < 4; ni++) {
            int col = n0 + wn + ni * 8 + 2 * tq;
            float b0v = bias[col], b1v = bias[col + 1];
            float x0 = cacc[mi][ni][0] + b0v;
            float x1 = cacc[mi][ni][1] + b1v;
            float x2 = cacc[mi][ni][2] + b0v;
            float x3 = cacc[mi][ni][3] + b1v;
            if (EPI == 1) {
                const float* r0 = resid + (size_t)row0 * ldn + col;
                const float* r1 = resid + (size_t)(row0 + 8) * ldn + col;
                x0 = 1.0f / (1.0f + expf(-(x0 + r0[0])));
                x1 = 1.0f / (1.0f + expf(-(x1 + r0[1])));
                x2 = 1.0f / (1.0f + expf(-(x2 + r1[0])));
                x3 = 1.0f / (1.0f + expf(-(x3 + r1[1])));
            }
            *(float2*)(C + (size_t)row0 * ldn + col)       = make_float2(x0, x1);
            *(float2*)(C + (size_t)(row0 + 8) * ldn + col) = make_float2(x2, x3);
            if (EPI == 0) {
                *(__half2*)(Ch + (size_t)row0 * ldn + col)       = __floats2half2_rn(x0, x1);
                *(__half2*)(Ch + (size_t)(row0 + 8) * ldn + col) = __floats2half2_rn(x2, x3);
            }
        }
    }
}

// ============================================================================
// q/k scalar projections: one warp per (row, head), reading fp32 feat_proj.
// ============================================================================
__global__ void qk_kernel(const float* __restrict__ qw, const float* __restrict__ qb,
                          const float* __restrict__ kw, const float* __restrict__ kb)
{
    int r = blockIdx.x;
    int t = threadIdx.x;
    int h = t >> 5, lane = t & 31;
    const float* row = g_fp + (size_t)r * 2048 + h * 256;
    float sq = 0.f, sk = 0.f;
    #pragma unroll
    for (int i = 0; i < 8; i++) {
        float f = row[lane + 32 * i];
        sq += f * qw[lane + 32 * i];
        sk += f * kw[lane + 32 * i];
    }
    #pragma unroll
    for (int o = 16; o > 0; o >>= 1) {
        sq += __shfl_down_sync(0xffffffffu, sq, o);
        sk += __shfl_down_sync(0xffffffffu, sk, o);
    }
    if (lane == 0) {
        int b = r >> 10, n = r & 1023;
        int bh = b * HEADSV + h;
        g_qv[bh * NN + n] = sq + qb[0];
        g_kv[bh * NN + n] = sk + kb[0];
    }
}

// ============================================================================
// Per-head factored-exp side tables (softmax shift-invariant; products <= 1):
//   m_i = leaky(q_i + kmax); g_qac=(q, e^{q-m}, e^{.01q-m}), g_kbd=(k, e^k, e^{.01k})
//   exp(leaky(q_i+k_j) - m_i) = (q_i+k_j>=0) ? A_i*B_j : C_i*D_j
// ============================================================================
__global__ void abcd_kernel()
{
    __shared__ float red[256];
    int bh = blockIdx.x, t = threadIdx.x;
    const float* kv = g_kv + bh * NN;
    float m = -1e30f;
    for (int n = t; n < NN; n += 256) m = fmaxf(m, kv[n]);
    red[t] = m; __syncthreads();
    for (int s = 128; s > 0; s >>= 1) {
        if (t < s) red[t] = fmaxf(red[t], red[t + s]);
        __syncthreads();
    }
    float kmax = red[0];
    const float* qv = g_qv + bh * NN;
    for (int n = t; n < NN; n += 256) {
        float q = qv[n], k = kv[n];
        float xm = q + kmax;
        float mi = (xm >= 0.f) ? xm : 0.01f * xm;
        g_qac[bh * NN + n] = make_float4(q, expf(q - mi), expf(0.01f * q - mi), 0.f);
        g_kbd[bh * NN + n] = make_float4(k, expf(k), expf(0.01f * k), 0.f);
    }
}

// ============================================================================
// fp16 tensor-core attention: CTA = (bh, 128-row i-tile), 512 threads,
// 16 warps (4m x 4n), warp tile 32x64. Per 32-row j-tile (triple-buffered
// cp.async fp16-V/kbd/mask staging):
//   1) build P[128][32] fp16 in smem (p computed fp32, rounded; masked entries
//      exactly 0, matching reference underflow); fp32 row-sums l in registers;
//   2) O += P @ V via m16n8k16 fp16 mma (ldmatrix fragments).
// Epilogue: O_row /= l_row, store fp16 to g_attn_h.
// ============================================================================
__global__ __launch_bounds__(512, 1)
void attn_kernel()
{
    extern __shared__ __align__(16) char sm_raw[];
    __half*   Vb   = (__half*)sm_raw;                        // [3][32][264]
    __half*   Pb   = Vb + 3 * 32 * 264;                      // [128][40]
    float4*   Kb   = (float4*)(Pb + 128 * 40);               // [3][32]
    unsigned* Mb   = (unsigned*)((char*)Kb + 3 * 512);       // [3][128]
    float4*   QAC  = (float4*)((char*)Mb + 3 * 512);         // [128]
    float*    l_pt = (float*)(QAC + 128);                    // [4][128]
    float*    l_sm = l_pt + 4 * 128;                         // [128]

    const int t    = threadIdx.x;
    const int lane = t & 31;
    const int wid  = t >> 5;
    const int wm   = (wid >> 2) * 32;     // 4 m-groups of 32 rows
    const int wn   = (wid & 3) * 64;      // 4 n-groups of 64 cols
    const int gq   = lane >> 2;
    const int tq   = lane & 3;
    const int lr16 = lane & 15;
    const int lblk = (lane >> 4) << 3;
    const int bh   = blockIdx.x;
    const int b    = bh >> 3, h = bh & 7;
    const int i0   = blockIdx.y * 128;
    const int bi0  = b * NN + i0;

    const unsigned sV0 = smem_u32(Vb);
    const unsigned sP0 = smem_u32(Pb);
    const unsigned sK0 = smem_u32(Kb);
    const unsigned sM0 = smem_u32(Mb);

    // P-build ownership: row = t & 127, col group pcg = t >> 7 (8 cols each)
    const int prow = t & 127, pcg = t >> 7;
    float pq, pA, pC, lr = 0.f;
    {
        float4 v = g_qac[bh * NN + i0 + prow];
        pq = v.x; pA = v.y; pC = v.z;
    }

    float cacc[2][8][4];
    #pragma unroll
    for (int mi = 0; mi < 2; mi++)
        #pragma unroll
        for (int ni = 0; ni < 8; ni++)
            #pragma unroll
            for (int r = 0; r < 4; r++) cacc[mi][ni][r] = 0.f;

    const __half*  vsrc = g_fph + ((size_t)b * NN * 2048 + h * 256);
    const float4*  ksrc = g_kbd + bh * NN;

    auto stage = [&](int jt, int s) {
        int j0 = jt * 32;
        unsigned sV = sV0 + s * (32 * 264 * 2);
        #pragma unroll
        for (int i = 0; i < 2; i++) {       // V: 32 rows x 256 halfs (32 chunks/row)
            int idx = t + i * 512;
            int row = idx >> 5, ch = idx & 31;
            cpasync16(sV + (row * 264 + ch * 8) * 2,
                      vsrc + (size_t)(j0 + row) * 2048 + ch * 8);
        }
        if (t < 32) {
            cpasync16(sK0 + s * 512 + t * 16, ksrc + j0 + t);
            cpasync16(sM0 + s * 512 + t * 16, g_m32 + jt * 8192 + bi0 + t * 4);
        }
        CP_COMMIT();
    };

    if (t < 128) QAC[t] = g_qac[bh * NN + i0 + t];
    stage(0, 0);
    stage(1, 1);

    int sl = 0;
    for (int jt = 0; jt < 32; jt++) {
        if (jt >= 30) CP_WAIT0(); else CP_WAIT1();
        __syncthreads();                 // tile jt visible; prev mma done by all
        if (jt + 2 < 32) stage(jt + 2, (sl + 2 >= 3) ? sl - 1 : sl + 2);

        // ---- build P tile (fp32 compute, fp16 store) ----
        {
            const unsigned* Ms = Mb + sl * 128;
            const float4*   Ks = Kb + sl * 32;
            unsigned m = Ms[prow];
            unsigned h2[4];
            #pragma unroll
            for (int cc = 0; cc < 4; cc++) {
                int j0c = pcg * 8 + cc * 2;
                float4 ka = Ks[j0c], kb2 = Ks[j0c + 1];
                float xa = pq + ka.x,  xb = pq + kb2.x;
                float p0 = (xa >= 0.f) ? pA * ka.y  : pC * ka.z;
                float p1 = (xb >= 0.f) ? pA * kb2.y : pC * kb2.z;
                p0 = (m & (1u << (j0c)))     ? p0 : 0.f;
                p1 = (m & (1u << (j0c + 1))) ? p1 : 0.f;
                lr += p0 + p1;
                __half2 hp = __floats2half2_rn(p0, p1);
                h2[cc] = *(unsigned*)&hp;
            }
            *(uint4*)(Pb + prow * 40 + pcg * 8) = make_uint4(h2[0], h2[1], h2[2], h2[3]);
        }
        __syncthreads();                 // P visible

        // ---- O += P @ V ----
        const unsigned sP_ = sP0;
        const unsigned sV_ = sV0 + sl * (32 * 264 * 2);
        #pragma unroll
        for (int ks = 0; ks < 2; ks++) {
            int kk = ks * 16;
            unsigned af[2][4], bf[8][2];
            #pragma unroll
            for (int mi = 0; mi < 2; mi++) {
                int row = wm + mi * 16 + lr16;
                ldm_x4(af[mi], sP_ + (row * 40 + kk + lblk) * 2);
            }
            #pragma unroll
            for (int np = 0; np < 4; np++) {
                unsigned r4[4];
                ldm_x4_t(r4, sV_ + ((kk + lr16) * 264 + wn + np * 16 + lblk) * 2);
                bf[np * 2][0] = r4[0]; bf[np * 2][1] = r4[1];
                bf[np * 2 + 1][0] = r4[2]; bf[np * 2 + 1][1] = r4[3];
            }
            #pragma unroll
            for (int mi = 0; mi < 2; mi++)
                #pragma unroll
                for (int ni = 0; ni < 8; ni++)
                    mma_f16(cacc[mi][ni], af[mi], bf[ni]);
        }
        sl = (sl == 2) ? 0 : sl + 1;
    }

    // ---- l reduction across the 4 col-groups ----
    l_pt[pcg * 128 + prow] = lr;
    __syncthreads();
    if (t < 128) l_sm[t] = (l_pt[t] + l_pt[128 + t]) + (l_pt[256 + t] + l_pt[384 + t]);
    __syncthreads();

    // ---- epilogue: normalize, store fp16 ----
    #pragma unroll
    for (int mi = 0; mi < 2; mi++) {
        int row0 = wm + mi * 16 + gq;
        float l0 = l_sm[row0], l1 = l_sm[row0 + 8];
        float inv0 = (l0 > 0.f) ? 1.0f / l0 : 0.f;
        float inv1 = (l1 > 0.f) ? 1.0f / l1 : 0.f;
        __half* o0 = g_attn_h + (size_t)(bi0 + row0) * 2048 + h * 256;
        __half* o1 = g_attn_h + (size_t)(bi0 + row0 + 8) * 2048 + h * 256;
        #pragma unroll
        for (int ni = 0; ni < 8; ni++) {
            int col = wn + ni * 8 + 2 * tq;
            *(__half2*)(o0 + col) = __floats2half2_rn(cacc[mi][ni][0] * inv0,
                                                      cacc[mi][ni][1] * inv0);
            *(__half2*)(o1 + col) = __floats2half2_rn(cacc[mi][ni][2] * inv1,
                                                      cacc[mi][ni][3] * inv1);
        }
    }
}

// ============================================================================
extern "C" void kernel_launch(void* const* d_in, const int* in_sizes, int n_in,
                              void* d_out, int out_size)
{
    const float* feats = (const float*)d_in[0];
    const float* adj   = (const float*)d_in[1];
    const float* fc_w  = (const float*)d_in[2];
    const float* fc_b  = (const float*)d_in[3];
    const float* q_w   = (const float*)d_in[4];
    const float* q_b   = (const float*)d_in[5];
    const float* k_w   = (const float*)d_in[6];
    const float* k_b   = (const float*)d_in[7];
    const float* fp_w  = (const float*)d_in[8];
    const float* fp_b  = (const float*)d_in[9];
    float* out = (float*)d_out;

    const int smem_mm = (2 * 128 * 40 + 2 * 32 * 136) * 2;   // 37888
    const int smem_at = (3 * 32 * 264 + 128 * 40) * 2        // V + P fp16
                      + 3 * 512 + 3 * 512                    // Kb + Mb
                      + 128 * 16 + 4 * 128 * 4 + 128 * 4;    // QAC + l_pt + l_sm
                                                             // = 66176

    cudaFuncSetAttribute(mma_gemm_h<0>, cudaFuncAttributeMaxDynamicSharedMemorySize, smem_mm);
    cudaFuncSetAttribute(mma_gemm_h<1>, cudaFuncAttributeMaxDynamicSharedMemorySize, smem_mm);
    cudaFuncSetAttribute(attn_kernel,   cudaFuncAttributeMaxDynamicSharedMemorySize, smem_at);

    float*  fp_buf = nullptr;
    __half *fph_buf = nullptr, *ath_buf = nullptr;
    __half *featsh = nullptr, *fcwh = nullptr, *fpwh = nullptr;
    cudaGetSymbolAddress((void**)&fp_buf,  g_fp);
    cudaGetSymbolAddress((void**)&fph_buf, g_fph);
    cudaGetSymbolAddress((void**)&ath_buf, g_attn_h);
    cudaGetSymbolAddress((void**)&featsh,  g_feats_h);
    cudaGetSymbolAddress((void**)&fcwh,    g_fcw_h);
    cudaGetSymbolAddress((void**)&fpwh,    g_fpw_h);

    // 0) fp16 input copies (same 11-bit mantissa as the tf32 path)
    cvt_kernel<<<(BSZ * NN * DIMV) / 1024, 256>>>(feats, featsh);
    cvt_kernel<<<(DIMV * DIMV * HEADSV) / 1024, 256>>>(fc_w, fcwh);
    cvt_kernel<<<(DIMV * HEADSV * DIMV) / 1024, 256>>>(fp_w, fpwh);

    // 1) adjacency bitmasks (shared across heads, transposed layout)
    mask_kernel<<<1024, 256>>>(adj);

    // 2) feat_proj = feats @ fc_w + fc_b (fp16 mma; dual fp32+fp16 output)
    mma_gemm_h<0><<<dim3(8192 / 128, 2048 / 128), 256, smem_mm>>>(
        featsh, fcwh, fc_b, nullptr, fp_buf, fph_buf, 256, 2048);

    // 3) q/k scalar projections (fp32 path)
    qk_kernel<<<8192, 256>>>(q_w, q_b, k_w, k_b);

    // 4) per-head kmax + factored exp side tables
    abcd_kernel<<<64, 256>>>();

    // 5) masked-softmax attention, P@V on fp16 tensor cores
    attn_kernel<<<dim3(64, 8), 512, smem_at>>>();

    // 6) out = sigmoid(attn_out @ fp_w + fp_b + feats) (fp16 mma)
    mma_gemm_h<1><<<dim3(8192 / 128, 256 / 128), 256, smem_mm>>>(
        ath_buf, fpwh, fp_b, feats, out, nullptr, 2048, 256);
}

// round 17
// speedup vs baseline: 4.7975x; 1.0393x over previous
#include <cuda_runtime.h>
#include <cuda_fp16.h>
#include <math.h>

#define DIMV 256
#define HEADSV 8
#define BSZ 8
#define NN 1024

typedef unsigned long long u64;

// ---- scratch (device globals: no allocations allowed) ----
__device__ __half g_fph[BSZ * NN * DIMV * HEADSV];    // 32 MB feat_proj fp16 (V source)
__device__ __half g_attn_h[BSZ * NN * DIMV * HEADSV]; // 32 MB attn out fp16 (GEMM3 A)
__device__ __half g_feats_h[BSZ * NN * DIMV];         //  4 MB feats fp16
__device__ __half g_fcw_h[DIMV * DIMV * HEADSV];      //  1 MB fc_w fp16
__device__ __half g_fpw_h[DIMV * HEADSV * DIMV];      //  1 MB fp_w fp16
__device__ float  g_qv[BSZ * HEADSV * NN];            // q partial sums (atomic, 2 contributors)
__device__ float  g_kv[BSZ * HEADSV * NN];
__device__ float4 g_kbd[BSZ * HEADSV * NN];           // (k, B=e^k, D=e^{.01k}, 0)
__device__ float4 g_qac[BSZ * HEADSV * NN];           // (q, A=e^{q-m}, C=e^{.01q-m}, 0)
__device__ unsigned g_m32[32 * BSZ * NN];             // masks, transposed [jt][bi]

// ---- cp.async helpers ----
__device__ __forceinline__ void cpasync16(unsigned s, const void* g) {
    asm volatile("cp.async.ca.shared.global [%0], [%1], 16;" :: "r"(s), "l"(g));
}
#define CP_COMMIT() asm volatile("cp.async.commit_group;" ::: "memory")
#define CP_WAIT1()  asm volatile("cp.async.wait_group 1;" ::: "memory")
#define CP_WAIT0()  asm volatile("cp.async.wait_group 0;" ::: "memory")

__device__ __forceinline__ unsigned smem_u32(const void* p) {
    unsigned a;
    asm("{ .reg .u64 t; cvta.to.shared.u64 t, %1; cvt.u32.u64 %0, t; }"
        : "=r"(a) : "l"(p));
    return a;
}
// ---- fp16 mma helpers ----
__device__ __forceinline__ void mma_f16(float* c, const unsigned* a, const unsigned* b) {
    asm("mma.sync.aligned.m16n8k16.row.col.f32.f16.f16.f32 "
        "{%0,%1,%2,%3}, {%4,%5,%6,%7}, {%8,%9}, {%0,%1,%2,%3};"
        : "+f"(c[0]), "+f"(c[1]), "+f"(c[2]), "+f"(c[3])
        : "r"(a[0]), "r"(a[1]), "r"(a[2]), "r"(a[3]), "r"(b[0]), "r"(b[1]));
}
__device__ __forceinline__ void ldm_x4(unsigned* r, unsigned addr) {
    asm volatile("ldmatrix.sync.aligned.m8n8.x4.shared.b16 {%0,%1,%2,%3}, [%4];"
        : "=r"(r[0]), "=r"(r[1]), "=r"(r[2]), "=r"(r[3]) : "r"(addr));
}
__device__ __forceinline__ void ldm_x4_t(unsigned* r, unsigned addr) {
    asm volatile("ldmatrix.sync.aligned.m8n8.x4.trans.shared.b16 {%0,%1,%2,%3}, [%4];"
        : "=r"(r[0]), "=r"(r[1]), "=r"(r[2]), "=r"(r[3]) : "r"(addr));
}

// ============================================================================
// fp32 -> fp16 conversion (inputs; 4 elems/thread, exact-size grids)
// ============================================================================
__global__ void cvt_kernel(const float* __restrict__ s, __half* __restrict__ d)
{
    int i = (blockIdx.x * 256 + threadIdx.x) * 4;
    float4 v = *(const float4*)(s + i);
    __half2* o = (__half2*)(d + i);
    o[0] = __floats2half2_rn(v.x, v.y);
    o[1] = __floats2half2_rn(v.z, v.w);
}

// ============================================================================
// Adjacency -> transposed 32-bit masks: warp per row, 32 j-tiles of 32 bits.
// ============================================================================
__global__ void mask_kernel(const float* __restrict__ adj)
{
    int bi   = blockIdx.x * 8 + (threadIdx.x >> 5);
    int lane = threadIdx.x & 31;
    const float* row = adj + (size_t)bi * 1024;
    #pragma unroll
    for (int jt = 0; jt < 32; jt++) {
        unsigned mm = __ballot_sync(0xffffffffu, row[jt * 32 + lane] != 0.f);
        if (lane == 0) g_m32[jt * 8192 + bi] = mm;
    }
}

// ============================================================================
// fp16 tensor-core GEMM: C = A @ B (+bias, epi), fp32 accumulate.
// CTA 128x128, 8 warps 64x32, K-chunk 32 (2 x k16) double-buffered cp.async.
// EPI 0 (GEMM1): +bias -> Ch fp16 only, PLUS fused q/k scalar projections:
//   per-thread partials over its 8 cols -> tq-shfl reduce -> smem reduce to
//   one partial per (row, 128-col CTA window) -> atomicAdd into g_qv/g_kv.
//   Exactly 2 atomic contributors per (row, head) (the two half-windows);
//   a+b == b+a in fp => bitwise deterministic.
// EPI 1 (GEMM3): +bias +resid, sigmoid -> C fp32.
// ============================================================================
template<int EPI>
__global__ __launch_bounds__(256, 2)
void mma_gemm_h(const __half* __restrict__ A, const __half* __restrict__ B,
                const float* __restrict__ bias, const float* __restrict__ resid,
                float* __restrict__ C, __half* __restrict__ Ch, int K, int ldn,
                const float* __restrict__ qw, const float* __restrict__ kw)
{
    extern __shared__ __align__(16) __half smh[];
    __half* As = smh;                   // [2][128][40]
    __half* Bs = smh + 2 * 128 * 40;    // [2][32][136]
    const unsigned sA0 = smem_u32(As);
    const unsigned sB0 = smem_u32(Bs);

    const int t    = threadIdx.x;
    const int lane = t & 31;
    const int wid  = t >> 5;
    const int wm   = (wid >> 2) * 64;
    const int wn   = (wid & 3) * 32;
    const int m0   = blockIdx.x * 128;
    const int n0   = blockIdx.y * 128;
    const int gq   = lane >> 2;
    const int tq   = lane & 3;
    const int lr16 = lane & 15;         // ldmatrix row select
    const int lblk = (lane >> 4) << 3;  // ldmatrix 8-col block select

    float cacc[4][4][4];
    #pragma unroll
    for (int mi = 0; mi < 4; mi++)
        #pragma unroll
        for (int ni = 0; ni < 4; ni++)
            #pragma unroll
            for (int r = 0; r < 4; r++) cacc[mi][ni][r] = 0.f;

    auto stage = [&](int kc, int buf) {
        #pragma unroll
        for (int i = 0; i < 2; i++) {       // A: 128 rows x 32 halfs
            int idx = t + i * 256;
            int row = idx >> 2, ch = idx & 3;
            cpasync16(sA0 + (buf * 5120 + row * 40 + ch * 8) * 2,
                      A + (size_t)(m0 + row) * K + kc + ch * 8);
        }
        #pragma unroll
        for (int i = 0; i < 2; i++) {       // B: 32 rows x 128 halfs
            int idx = t + i * 256;
            int row = idx >> 4, ch = idx & 15;
            cpasync16(sB0 + (buf * 4352 + row * 136 + ch * 8) * 2,
                      B + (size_t)(kc + row) * ldn + n0 + ch * 8);
        }
        CP_COMMIT();
    };

    const int nch = K / 32;
    stage(0, 0);
    for (int c = 0; c < nch; c++) {
        CP_WAIT0();
        __syncthreads();
        if (c + 1 < nch) stage((c + 1) * 32, (c + 1) & 1);

        const unsigned sA_ = sA0 + (c & 1) * 5120 * 2;
        const unsigned sB_ = sB0 + (c & 1) * 4352 * 2;

        #pragma unroll
        for (int ks = 0; ks < 2; ks++) {
            int kk = ks * 16;
            unsigned af[4][4], bf[4][2];
            #pragma unroll
            for (int mi = 0; mi < 4; mi++) {
                int row = wm + mi * 16 + lr16;
                ldm_x4(af[mi], sA_ + (row * 40 + kk + lblk) * 2);
            }
            #pragma unroll
            for (int np = 0; np < 2; np++) {
                unsigned r4[4];
                ldm_x4_t(r4, sB_ + ((kk + lr16) * 136 + wn + np * 16 + lblk) * 2);
                bf[np * 2][0] = r4[0]; bf[np * 2][1] = r4[1];
                bf[np * 2 + 1][0] = r4[2]; bf[np * 2 + 1][1] = r4[3];
            }
            #pragma unroll
            for (int mi = 0; mi < 4; mi++)
                #pragma unroll
                for (int ni = 0; ni < 4; ni++)
                    mma_f16(cacc[mi][ni], af[mi], bf[ni]);
        }
        __syncthreads();
    }

    float sqa[4][2], ska[4][2];
    if (EPI == 0) {
        #pragma unroll
        for (int mi = 0; mi < 4; mi++) {
            sqa[mi][0] = sqa[mi][1] = 0.f;
            ska[mi][0] = ska[mi][1] = 0.f;
        }
    }

    #pragma unroll
    for (int mi = 0; mi < 4; mi++) {
        int row0 = m0 + wm + mi * 16 + gq;
        #pragma unroll
        for (int ni = 0; ni < 4; ni++) {
            int col = n0 + wn + ni * 8 + 2 * tq;
            float b0v = bias[col], b1v = bias[col + 1];
            float x0 = cacc[mi][ni][0] + b0v;
            float x1 = cacc[mi][ni][1] + b1v;
            float x2 = cacc[mi][ni][2] + b0v;
            float x3 = cacc[mi][ni][3] + b1v;
            if (EPI == 1) {
                const float* r0 = resid + (size_t)row0 * ldn + col;
                const float* r1 = resid + (size_t)(row0 + 8) * ldn + col;
                x0 = 1.0f / (1.0f + expf(-(x0 + r0[0])));
                x1 = 1.0f / (1.0f + expf(-(x1 + r0[1])));
                x2 = 1.0f / (1.0f + expf(-(x2 + r1[0])));
                x3 = 1.0f / (1.0f + expf(-(x3 + r1[1])));
                *(float2*)(C + (size_t)row0 * ldn + col)       = make_float2(x0, x1);
                *(float2*)(C + (size_t)(row0 + 8) * ldn + col) = make_float2(x2, x3);
            }
            if (EPI == 0) {
                *(__half2*)(Ch + (size_t)row0 * ldn + col)       = __floats2half2_rn(x0, x1);
                *(__half2*)(Ch + (size_t)(row0 + 8) * ldn + col) = __floats2half2_rn(x2, x3);
                int co = col & 255;                 // head-local column
                float qw0 = qw[co], qw1 = qw[co + 1];
                float kw0 = kw[co], kw1 = kw[co + 1];
                sqa[mi][0] += x0 * qw0 + x1 * qw1;
                sqa[mi][1] += x2 * qw0 + x3 * qw1;
                ska[mi][0] += x0 * kw0 + x1 * kw1;
                ska[mi][1] += x2 * kw0 + x3 * kw1;
            }
        }
    }

    if (EPI == 0) {
        // tq-lane reduction (lanes grouped {gq*4+tq}, xor over bits 0..1)
        float* qpart = (float*)smh;          // [128][4]
        float* kpart = qpart + 512;          // [128][4]
        #pragma unroll
        for (int mi = 0; mi < 4; mi++)
            #pragma unroll
            for (int hh = 0; hh < 2; hh++) {
                float vq = sqa[mi][hh], vk = ska[mi][hh];
                vq += __shfl_xor_sync(0xffffffffu, vq, 1);
                vq += __shfl_xor_sync(0xffffffffu, vq, 2);
                vk += __shfl_xor_sync(0xffffffffu, vk, 1);
                vk += __shfl_xor_sync(0xffffffffu, vk, 2);
                if (tq == 0) {
                    int rowl = wm + mi * 16 + gq + hh * 8;
                    qpart[rowl * 4 + (wid & 3)] = vq;
                    kpart[rowl * 4 + (wid & 3)] = vk;
                }
            }
        __syncthreads();
        if (t < 128) {
            float sq4 = (qpart[t * 4] + qpart[t * 4 + 1]) + (qpart[t * 4 + 2] + qpart[t * 4 + 3]);
            float sk4 = (kpart[t * 4] + kpart[t * 4 + 1]) + (kpart[t * 4 + 2] + kpart[t * 4 + 3]);
            int m = m0 + t;
            int b = m >> 10, n = m & 1023;
            int head = n0 >> 8;
            atomicAdd(&g_qv[(b * HEADSV + head) * NN + n], sq4);
            atomicAdd(&g_kv[(b * HEADSV + head) * NN + n], sk4);
        }
    }
}

// ============================================================================
// Per-head factored-exp side tables (softmax shift-invariant; products <= 1):
// Adds q/k biases (q partials arrive bias-less from the fused GEMM1 epilogue).
//   m_i = leaky(q_i + kmax); g_qac=(q, e^{q-m}, e^{.01q-m}), g_kbd=(k, e^k, e^{.01k})
//   exp(leaky(q_i+k_j) - m_i) = (q_i+k_j>=0) ? A_i*B_j : C_i*D_j
// ============================================================================
__global__ void abcd_kernel(const float* __restrict__ qb, const float* __restrict__ kb)
{
    __shared__ float red[256];
    int bh = blockIdx.x, t = threadIdx.x;
    float qbv = qb[0], kbv = kb[0];
    const float* kv = g_kv + bh * NN;
    float m = -1e30f;
    for (int n = t; n < NN; n += 256) m = fmaxf(m, kv[n] + kbv);
    red[t] = m; __syncthreads();
    for (int s = 128; s > 0; s >>= 1) {
        if (t < s) red[t] = fmaxf(red[t], red[t + s]);
        __syncthreads();
    }
    float kmax = red[0];
    const float* qv = g_qv + bh * NN;
    for (int n = t; n < NN; n += 256) {
        float q = qv[n] + qbv, k = kv[n] + kbv;
        float xm = q + kmax;
        float mi = (xm >= 0.f) ? xm : 0.01f * xm;
        g_qac[bh * NN + n] = make_float4(q, expf(q - mi), expf(0.01f * q - mi), 0.f);
        g_kbd[bh * NN + n] = make_float4(k, expf(k), expf(0.01f * k), 0.f);
    }
}

// ============================================================================
// fp16 tensor-core attention (validated R16): CTA = (bh, 128-row i-tile),
// 512 threads, 16 warps (4m x 4n), warp tile 32x64. Triple-buffered cp.async
// V/kbd/mask staging; P built fp32 -> fp16 in smem (masked entries exactly 0);
// fp32 row-sums l; O += P @ V via m16n8k16; epilogue O/l -> fp16.
// ============================================================================
__global__ __launch_bounds__(512, 1)
void attn_kernel()
{
    extern __shared__ __align__(16) char sm_raw[];
    __half*   Vb   = (__half*)sm_raw;                        // [3][32][264]
    __half*   Pb   = Vb + 3 * 32 * 264;                      // [128][40]
    float4*   Kb   = (float4*)(Pb + 128 * 40);               // [3][32]
    unsigned* Mb   = (unsigned*)((char*)Kb + 3 * 512);       // [3][128]
    float4*   QAC  = (float4*)((char*)Mb + 3 * 512);         // [128]
    float*    l_pt = (float*)(QAC + 128);                    // [4][128]
    float*    l_sm = l_pt + 4 * 128;                         // [128]

    const int t    = threadIdx.x;
    const int lane = t & 31;
    const int wid  = t >> 5;
    const int wm   = (wid >> 2) * 32;
    const int wn   = (wid & 3) * 64;
    const int gq   = lane >> 2;
    const int tq   = lane & 3;
    const int lr16 = lane & 15;
    const int lblk = (lane >> 4) << 3;
    const int bh   = blockIdx.x;
    const int b    = bh >> 3, h = bh & 7;
    const int i0   = blockIdx.y * 128;
    const int bi0  = b * NN + i0;

    const unsigned sV0 = smem_u32(Vb);
    const unsigned sP0 = smem_u32(Pb);
    const unsigned sK0 = smem_u32(Kb);
    const unsigned sM0 = smem_u32(Mb);

    const int prow = t & 127, pcg = t >> 7;
    float pq, pA, pC, lr = 0.f;
    {
        float4 v = g_qac[bh * NN + i0 + prow];
        pq = v.x; pA = v.y; pC = v.z;
    }

    float cacc[2][8][4];
    #pragma unroll
    for (int mi = 0; mi < 2; mi++)
        #pragma unroll
        for (int ni = 0; ni < 8; ni++)
            #pragma unroll
            for (int r = 0; r < 4; r++) cacc[mi][ni][r] = 0.f;

    const __half*  vsrc = g_fph + ((size_t)b * NN * 2048 + h * 256);
    const float4*  ksrc = g_kbd + bh * NN;

    auto stage = [&](int jt, int s) {
        int j0 = jt * 32;
        unsigned sV = sV0 + s * (32 * 264 * 2);
        #pragma unroll
        for (int i = 0; i < 2; i++) {
            int idx = t + i * 512;
            int row = idx >> 5, ch = idx & 31;
            cpasync16(sV + (row * 264 + ch * 8) * 2,
                      vsrc + (size_t)(j0 + row) * 2048 + ch * 8);
        }
        if (t < 32) {
            cpasync16(sK0 + s * 512 + t * 16, ksrc + j0 + t);
            cpasync16(sM0 + s * 512 + t * 16, g_m32 + jt * 8192 + bi0 + t * 4);
        }
        CP_COMMIT();
    };

    if (t < 128) QAC[t] = g_qac[bh * NN + i0 + t];
    stage(0, 0);
    stage(1, 1);

    int sl = 0;
    for (int jt = 0; jt < 32; jt++) {
        if (jt >= 30) CP_WAIT0(); else CP_WAIT1();
        __syncthreads();
        if (jt + 2 < 32) stage(jt + 2, (sl + 2 >= 3) ? sl - 1 : sl + 2);

        {
            const unsigned* Ms = Mb + sl * 128;
            const float4*   Ks = Kb + sl * 32;
            unsigned m = Ms[prow];
            unsigned h2[4];
            #pragma unroll
            for (int cc = 0; cc < 4; cc++) {
                int j0c = pcg * 8 + cc * 2;
                float4 ka = Ks[j0c], kb2 = Ks[j0c + 1];
                float xa = pq + ka.x,  xb = pq + kb2.x;
                float p0 = (xa >= 0.f) ? pA * ka.y  : pC * ka.z;
                float p1 = (xb >= 0.f) ? pA * kb2.y : pC * kb2.z;
                p0 = (m & (1u << (j0c)))     ? p0 : 0.f;
                p1 = (m & (1u << (j0c + 1))) ? p1 : 0.f;
                lr += p0 + p1;
                __half2 hp = __floats2half2_rn(p0, p1);
                h2[cc] = *(unsigned*)&hp;
            }
            *(uint4*)(Pb + prow * 40 + pcg * 8) = make_uint4(h2[0], h2[1], h2[2], h2[3]);
        }
        __syncthreads();

        const unsigned sV_ = sV0 + sl * (32 * 264 * 2);
        #pragma unroll
        for (int ks = 0; ks < 2; ks++) {
            int kk = ks * 16;
            unsigned af[2][4], bf[8][2];
            #pragma unroll
            for (int mi = 0; mi < 2; mi++) {
                int row = wm + mi * 16 + lr16;
                ldm_x4(af[mi], sP0 + (row * 40 + kk + lblk) * 2);
            }
            #pragma unroll
            for (int np = 0; np < 4; np++) {
                unsigned r4[4];
                ldm_x4_t(r4, sV_ + ((kk + lr16) * 264 + wn + np * 16 + lblk) * 2);
                bf[np * 2][0] = r4[0]; bf[np * 2][1] = r4[1];
                bf[np * 2 + 1][0] = r4[2]; bf[np * 2 + 1][1] = r4[3];
            }
            #pragma unroll
            for (int mi = 0; mi < 2; mi++)
                #pragma unroll
                for (int ni = 0; ni < 8; ni++)
                    mma_f16(cacc[mi][ni], af[mi], bf[ni]);
        }
        sl = (sl == 2) ? 0 : sl + 1;
    }

    l_pt[pcg * 128 + prow] = lr;
    __syncthreads();
    if (t < 128) l_sm[t] = (l_pt[t] + l_pt[128 + t]) + (l_pt[256 + t] + l_pt[384 + t]);
    __syncthreads();

    #pragma unroll
    for (int mi = 0; mi < 2; mi++) {
        int row0 = wm + mi * 16 + gq;
        float l0 = l_sm[row0], l1 = l_sm[row0 + 8];
        float inv0 = (l0 > 0.f) ? 1.0f / l0 : 0.f;
        float inv1 = (l1 > 0.f) ? 1.0f / l1 : 0.f;
        __half* o0 = g_attn_h + (size_t)(bi0 + row0) * 2048 + h * 256;
        __half* o1 = g_attn_h + (size_t)(bi0 + row0 + 8) * 2048 + h * 256;
        #pragma unroll
        for (int ni = 0; ni < 8; ni++) {
            int col = wn + ni * 8 + 2 * tq;
            *(__half2*)(o0 + col) = __floats2half2_rn(cacc[mi][ni][0] * inv0,
                                                      cacc[mi][ni][1] * inv0);
            *(__half2*)(o1 + col) = __floats2half2_rn(cacc[mi][ni][2] * inv1,
                                                      cacc[mi][ni][3] * inv1);
        }
    }
}

// ============================================================================
extern "C" void kernel_launch(void* const* d_in, const int* in_sizes, int n_in,
                              void* d_out, int out_size)
{
    const float* feats = (const float*)d_in[0];
    const float* adj   = (const float*)d_in[1];
    const float* fc_w  = (const float*)d_in[2];
    const float* fc_b  = (const float*)d_in[3];
    const float* q_w   = (const float*)d_in[4];
    const float* q_b   = (const float*)d_in[5];
    const float* k_w   = (const float*)d_in[6];
    const float* k_b   = (const float*)d_in[7];
    const float* fp_w  = (const float*)d_in[8];
    const float* fp_b  = (const float*)d_in[9];
    float* out = (float*)d_out;

    const int smem_mm = (2 * 128 * 40 + 2 * 32 * 136) * 2;   // 37888
    const int smem_at = (3 * 32 * 264 + 128 * 40) * 2
                      + 3 * 512 + 3 * 512
                      + 128 * 16 + 4 * 128 * 4 + 128 * 4;    // 66176

    cudaFuncSetAttribute(mma_gemm_h<0>, cudaFuncAttributeMaxDynamicSharedMemorySize, smem_mm);
    cudaFuncSetAttribute(mma_gemm_h<1>, cudaFuncAttributeMaxDynamicSharedMemorySize, smem_mm);
    cudaFuncSetAttribute(attn_kernel,   cudaFuncAttributeMaxDynamicSharedMemorySize, smem_at);

    __half *fph_buf = nullptr, *ath_buf = nullptr;
    __half *featsh = nullptr, *fcwh = nullptr, *fpwh = nullptr;
    float  *qv_ptr = nullptr, *kv_ptr = nullptr;
    cudaGetSymbolAddress((void**)&fph_buf, g_fph);
    cudaGetSymbolAddress((void**)&ath_buf, g_attn_h);
    cudaGetSymbolAddress((void**)&featsh,  g_feats_h);
    cudaGetSymbolAddress((void**)&fcwh,    g_fcw_h);
    cudaGetSymbolAddress((void**)&fpwh,    g_fpw_h);
    cudaGetSymbolAddress((void**)&qv_ptr,  g_qv);
    cudaGetSymbolAddress((void**)&kv_ptr,  g_kv);

    // 0) zero q/k partial-sum accumulators (async memset: graph-capturable)
    cudaMemsetAsync(qv_ptr, 0, BSZ * HEADSV * NN * sizeof(float));
    cudaMemsetAsync(kv_ptr, 0, BSZ * HEADSV * NN * sizeof(float));

    // 0b) fp16 input copies (same 11-bit mantissa as tf32)
    cvt_kernel<<<(BSZ * NN * DIMV) / 1024, 256>>>(feats, featsh);
    cvt_kernel<<<(DIMV * DIMV * HEADSV) / 1024, 256>>>(fc_w, fcwh);
    cvt_kernel<<<(DIMV * HEADSV * DIMV) / 1024, 256>>>(fp_w, fpwh);

    // 1) adjacency bitmasks (shared across heads, transposed layout)
    mask_kernel<<<1024, 256>>>(adj);

    // 2) feat_proj = feats @ fc_w + fc_b (fp16 mma; fp16 output) + fused q/k
    mma_gemm_h<0><<<dim3(8192 / 128, 2048 / 128), 256, smem_mm>>>(
        featsh, fcwh, fc_b, nullptr, nullptr, fph_buf, 256, 2048, q_w, k_w);

    // 3) per-head kmax + factored exp side tables (adds q/k biases)
    abcd_kernel<<<64, 256>>>(q_b, k_b);

    // 4) masked-softmax attention, P@V on fp16 tensor cores
    attn_kernel<<<dim3(64, 8), 512, smem_at>>>();

    // 5) out = sigmoid(attn_out @ fp_w + fp_b + feats) (fp16 mma)
    mma_gemm_h<1><<<dim3(8192 / 128, 256 / 128), 256, smem_mm>>>(
        ath_buf, fpwh, fp_b, feats, out, nullptr, 2048, 256, nullptr, nullptr);
}